// round 1
// baseline (speedup 1.0000x reference)
#include <cuda_runtime.h>

#define BATCH 2
#define SEQ   2048
#define DIM   1024
#define HEADS 16
#define HDIM  64
#define SCALE 0.125f   // 64^{-0.5}
#define NSPLIT 32

// ---------------- scratch (__device__ globals; no allocation allowed) ----------------
__device__ float g_partial[BATCH * NSPLIT * DIM];
__device__ float g_xavg[BATCH * DIM];
__device__ float g_kavg[BATCH * DIM];            // [b][h*64+d]
__device__ float g_u[BATCH * HEADS * DIM];       // [b][h][c]
__device__ float g_z[BATCH * HEADS * SEQ];       // z then attn in-place
__device__ float g_v[(size_t)BATCH * SEQ * DIM];
__device__ float g_outh[(size_t)BATCH * SEQ * DIM];

// ---------------- K1a: partial column sums of x over n ----------------
__global__ void colsum_part(const float* __restrict__ x) {
    int c = blockIdx.x * 256 + threadIdx.x;
    int b = blockIdx.y, s = blockIdx.z;
    const float* xp = x + ((size_t)b * SEQ + (size_t)s * (SEQ / NSPLIT)) * DIM + c;
    float sum = 0.f;
    #pragma unroll 8
    for (int n = 0; n < SEQ / NSPLIT; n++) sum += xp[(size_t)n * DIM];
    g_partial[(b * NSPLIT + s) * DIM + c] = sum;
}

// ---------------- K1b: finalize x_avg ----------------
__global__ void colsum_final() {
    int i = blockIdx.x * 256 + threadIdx.x;   // b*DIM + c
    int b = i / DIM, c = i % DIM;
    float s = 0.f;
    #pragma unroll
    for (int p = 0; p < NSPLIT; p++) s += g_partial[(b * NSPLIT + p) * DIM + c];
    g_xavg[i] = s * (1.0f / SEQ);
}

// ---------------- K2: k_avg[b][co] = x_avg[b] . wk[co,:]  (warp per output) ----------------
__global__ void kavg_kernel(const float* __restrict__ wk) {
    int w = (blockIdx.x * blockDim.x + threadIdx.x) >> 5;
    int lane = threadIdx.x & 31;
    int b = w / DIM, co = w % DIM;
    const float* wr = wk + (size_t)co * DIM;
    const float* xa = g_xavg + b * DIM;
    float s = 0.f;
    #pragma unroll 4
    for (int c = lane; c < DIM; c += 32) s += wr[c] * xa[c];
    #pragma unroll
    for (int o = 16; o > 0; o >>= 1) s += __shfl_xor_sync(0xffffffffu, s, o);
    if (lane == 0) g_kavg[b * DIM + co] = s;
}

// ---------------- K3: u[b,h,c] = sum_d k_avg[b,h,d] * wq[h*64+d, c] ----------------
__global__ void u_kernel(const float* __restrict__ wq) {
    int c = blockIdx.x * 256 + threadIdx.x;
    int h = blockIdx.y, b = blockIdx.z;
    __shared__ float ka[HDIM];
    if (threadIdx.x < HDIM) ka[threadIdx.x] = g_kavg[b * DIM + h * HDIM + threadIdx.x];
    __syncthreads();
    float s = 0.f;
    #pragma unroll
    for (int d = 0; d < HDIM; d++) s += ka[d] * wq[(size_t)(h * HDIM + d) * DIM + c];
    g_u[(b * HEADS + h) * DIM + c] = s;
}

// ---------------- K4: z[b,h,n] = scale * x[b,n,:] . u[b,h,:]  (warp per output) ----------------
__global__ void z_kernel(const float* __restrict__ x) {
    int w = (blockIdx.x * blockDim.x + threadIdx.x) >> 5;  // 0..B*H*SEQ-1
    int lane = threadIdx.x & 31;
    int n = w % SEQ;
    int bh = w / SEQ;
    int b = bh / HEADS;
    const float* xr = x + ((size_t)b * SEQ + n) * DIM;
    const float* ur = g_u + (size_t)bh * DIM;
    float s = 0.f;
    #pragma unroll 4
    for (int c = lane; c < DIM; c += 32) s += xr[c] * ur[c];
    #pragma unroll
    for (int o = 16; o > 0; o >>= 1) s += __shfl_xor_sync(0xffffffffu, s, o);
    if (lane == 0) g_z[w] = s * SCALE;
}

// ---------------- K5: softmax over n per (b,h), in-place on g_z ----------------
__global__ void softmax_kernel() {
    int bh = blockIdx.x;
    float* z = g_z + (size_t)bh * SEQ;
    __shared__ float red[256];
    int t = threadIdx.x;
    float m = -1e30f;
    for (int i = t; i < SEQ; i += 256) m = fmaxf(m, z[i]);
    red[t] = m; __syncthreads();
    for (int o = 128; o > 0; o >>= 1) { if (t < o) red[t] = fmaxf(red[t], red[t + o]); __syncthreads(); }
    m = red[0]; __syncthreads();
    float s = 0.f;
    for (int i = t; i < SEQ; i += 256) { float e = __expf(z[i] - m); z[i] = e; s += e; }
    red[t] = s; __syncthreads();
    for (int o = 128; o > 0; o >>= 1) { if (t < o) red[t] += red[t + o]; __syncthreads(); }
    float inv = 1.0f / red[0];
    for (int i = t; i < SEQ; i += 256) z[i] *= inv;
}

// ---------------- K6: SGEMM  C[M,N] = A[M,K] @ W[N,K]^T (+bias) ----------------
#define BM 128
#define BN 128
#define BKK 8
__global__ __launch_bounds__(256) void sgemm_abt(
    const float* __restrict__ A, const float* __restrict__ W,
    const float* __restrict__ bias, float* __restrict__ C,
    int M, int N, int K)
{
    __shared__ float As[BKK][BM];
    __shared__ float Bs[BKK][BN];
    int tid = threadIdx.x;
    int bx = blockIdx.x;  // N tile
    int by = blockIdx.y;  // M tile

    int lr = tid >> 1;           // 0..127
    int lc = (tid & 1) * 4;      // 0 or 4
    const float* Ap = A + ((size_t)(by * BM + lr)) * K + lc;
    const float* Wp = W + ((size_t)(bx * BN + lr)) * K + lc;

    int tr = tid >> 4;   // 0..15
    int tc = tid & 15;   // 0..15

    float acc[8][8] = {};
    float ar[8], br[8];

    for (int k0 = 0; k0 < K; k0 += BKK) {
        float4 a = *(const float4*)(Ap + k0);
        float4 b = *(const float4*)(Wp + k0);
        As[lc + 0][lr] = a.x; As[lc + 1][lr] = a.y; As[lc + 2][lr] = a.z; As[lc + 3][lr] = a.w;
        Bs[lc + 0][lr] = b.x; Bs[lc + 1][lr] = b.y; Bs[lc + 2][lr] = b.z; Bs[lc + 3][lr] = b.w;
        __syncthreads();
        #pragma unroll
        for (int k = 0; k < BKK; k++) {
            #pragma unroll
            for (int i = 0; i < 8; i++) ar[i] = As[k][tr * 8 + i];
            #pragma unroll
            for (int j = 0; j < 8; j++) br[j] = Bs[k][tc * 8 + j];
            #pragma unroll
            for (int i = 0; i < 8; i++)
                #pragma unroll
                for (int j = 0; j < 8; j++)
                    acc[i][j] += ar[i] * br[j];
        }
        __syncthreads();
    }

    #pragma unroll
    for (int i = 0; i < 8; i++) {
        int row = by * BM + tr * 8 + i;
        float* Crow = C + (size_t)row * N + bx * BN + tc * 8;
        #pragma unroll
        for (int j = 0; j < 8; j++) {
            float v = acc[i][j];
            if (bias) v += bias[bx * BN + tc * 8 + j];
            Crow[j] = v;
        }
    }
}

// ---------------- K7: circular conv  out[i] = sum_m attn[m] * v[(i+m) mod N] ----------------
#define TI 64
#define TMC 64
__global__ __launch_bounds__(256) void conv_kernel() {
    int i0 = blockIdx.x * TI;        // 32 i-tiles
    int bh = blockIdx.y;             // 0..31
    int b = bh >> 4, h = bh & 15;
    const float* attn  = g_z + (size_t)bh * SEQ;
    const float* vbase = g_v + ((size_t)b * SEQ) * DIM + h * HDIM;

    __shared__ float vs[TI + TMC][HDIM];  // 128 x 64 f32 = 32 KB
    __shared__ float as[TMC];

    int tid = threadIdx.x;
    int tiy = tid >> 4;   // 0..15 -> i rows tiy*4..+3
    int tix = tid & 15;   // 0..15 -> d cols tix*4..+3

    float acc[4][4] = {};

    int lr = tid >> 1;            // row 0..127 to load
    int lq = (tid & 1) * 32;      // col offset 0 or 32

    for (int m0 = 0; m0 < SEQ; m0 += TMC) {
        if (tid < TMC) as[tid] = attn[m0 + tid];
        int j = (i0 + m0 + lr) & (SEQ - 1);
        const float4* src = (const float4*)(vbase + (size_t)j * DIM + lq);
        float4* dst = (float4*)&vs[lr][lq];
        #pragma unroll
        for (int q = 0; q < 8; q++) dst[q] = src[q];
        __syncthreads();
        #pragma unroll 4
        for (int m = 0; m < TMC; m++) {
            float am = as[m];
            #pragma unroll
            for (int ii = 0; ii < 4; ii++) {
                const float* vr = &vs[tiy * 4 + ii + m][tix * 4];
                #pragma unroll
                for (int dd = 0; dd < 4; dd++)
                    acc[ii][dd] += am * vr[dd];
            }
        }
        __syncthreads();
    }

    #pragma unroll
    for (int ii = 0; ii < 4; ii++) {
        float* orow = g_outh + ((size_t)b * SEQ + i0 + tiy * 4 + ii) * DIM + h * HDIM + tix * 4;
        #pragma unroll
        for (int dd = 0; dd < 4; dd++) orow[dd] = acc[ii][dd];
    }
}

// ---------------- launch ----------------
static float* sym_addr_v()    { void* p = nullptr; cudaGetSymbolAddress(&p, g_v);    return (float*)p; }
static float* sym_addr_outh() { void* p = nullptr; cudaGetSymbolAddress(&p, g_outh); return (float*)p; }

extern "C" void kernel_launch(void* const* d_in, const int* in_sizes, int n_in,
                              void* d_out, int out_size) {
    const float* x  = (const float*)d_in[0];
    const float* wq = (const float*)d_in[1];
    const float* wk = (const float*)d_in[2];
    const float* wv = (const float*)d_in[3];
    const float* wp = (const float*)d_in[4];
    const float* bp = (const float*)d_in[5];
    float* out = (float*)d_out;

    float* gv = sym_addr_v();
    float* go = sym_addr_outh();

    // attention-weight path (tiny, thanks to algebraic folding)
    colsum_part<<<dim3(DIM / 256, BATCH, NSPLIT), 256>>>(x);
    colsum_final<<<(BATCH * DIM) / 256, 256>>>();
    kavg_kernel<<<(BATCH * DIM * 32) / 256, 256>>>(wk);
    u_kernel<<<dim3(DIM / 256, HEADS, BATCH), 256>>>(wq);
    z_kernel<<<(BATCH * HEADS * SEQ * 32) / 256, 256>>>(x);
    softmax_kernel<<<BATCH * HEADS, 256>>>();

    // v projection: [B*N, C] @ wv^T
    sgemm_abt<<<dim3(DIM / BN, (BATCH * SEQ) / BM), 256>>>(x, wv, nullptr, gv,
                                                           BATCH * SEQ, DIM, DIM);
    // circular convolution per (b,h), writes [B,N,C] head-interleaved layout
    conv_kernel<<<dim3(SEQ / TI, BATCH * HEADS), 256>>>();

    // output projection with bias
    sgemm_abt<<<dim3(DIM / BN, (BATCH * SEQ) / BM), 256>>>(go, wp, bp, out,
                                                           BATCH * SEQ, DIM, DIM);
}

// round 3
// speedup vs baseline: 3.6216x; 3.6216x over previous
#include <cuda_runtime.h>
#include <cuda_bf16.h>
#include <cstdint>

#define BATCH 2
#define SEQ   2048
#define DIM   1024
#define HEADS 16
#define HDIM  64
#define SCALE 0.125f
#define NSPLIT 32
#define MTOT  4096
#define PPITCH 40

typedef __nv_bfloat16 bf16;

// ---------------- scratch ----------------
__device__ float g_partial[BATCH * NSPLIT * DIM];
__device__ float g_xavg[BATCH * DIM];
__device__ float g_kavg[BATCH * DIM];
__device__ float g_u[BATCH * HEADS * DIM];
__device__ float g_z[BATCH * HEADS * SEQ];
__device__ float g_v[(size_t)MTOT * DIM];
__device__ float g_outh[(size_t)MTOT * DIM];

__device__ bf16 g_xhi[(size_t)MTOT * DIM];
__device__ bf16 g_xlo[(size_t)MTOT * DIM];
__device__ bf16 g_wvhi[DIM * DIM];
__device__ bf16 g_wvlo[DIM * DIM];
__device__ bf16 g_wphi[DIM * DIM];
__device__ bf16 g_wplo[DIM * DIM];
__device__ bf16 g_vthi[32 * HDIM * SEQ];
__device__ bf16 g_vtlo[32 * HDIM * SEQ];
__device__ bf16 g_a2hi[32 * 4224];
__device__ bf16 g_a2lo[32 * 4224];
__device__ bf16 g_ohhi[(size_t)MTOT * DIM];
__device__ bf16 g_ohlo[(size_t)MTOT * DIM];

// ---------------- PTX helpers ----------------
__device__ __forceinline__ unsigned smem_u32(const void* p) {
    return (unsigned)__cvta_generic_to_shared(p);
}

__device__ __forceinline__ void ldsm_x4(unsigned& r0, unsigned& r1, unsigned& r2, unsigned& r3, unsigned a) {
    asm volatile("ldmatrix.sync.aligned.m8n8.x4.shared.b16 {%0,%1,%2,%3}, [%4];"
                 : "=r"(r0), "=r"(r1), "=r"(r2), "=r"(r3) : "r"(a));
}

__device__ __forceinline__ void mma_bf16(float* c, unsigned a0, unsigned a1, unsigned a2, unsigned a3,
                                         unsigned b0, unsigned b1) {
    asm volatile("mma.sync.aligned.m16n8k16.row.col.f32.bf16.bf16.f32 "
                 "{%0,%1,%2,%3}, {%4,%5,%6,%7}, {%8,%9}, {%0,%1,%2,%3};"
                 : "+f"(c[0]), "+f"(c[1]), "+f"(c[2]), "+f"(c[3])
                 : "r"(a0), "r"(a1), "r"(a2), "r"(a3), "r"(b0), "r"(b1));
}

__device__ __forceinline__ void split1(float v, bf16& h, bf16& l) {
    h = __float2bfloat16(v);
    l = __float2bfloat16(v - __bfloat162float(h));
}

// ---------------- small attention-weight path ----------------
__global__ void colsum_part(const float* __restrict__ x) {
    int c = blockIdx.x * 256 + threadIdx.x;
    int b = blockIdx.y, s = blockIdx.z;
    const float* xp = x + ((size_t)b * SEQ + (size_t)s * (SEQ / NSPLIT)) * DIM + c;
    float sum = 0.f;
    #pragma unroll 8
    for (int n = 0; n < SEQ / NSPLIT; n++) sum += xp[(size_t)n * DIM];
    g_partial[(b * NSPLIT + s) * DIM + c] = sum;
}

__global__ void colsum_final() {
    int i = blockIdx.x * 256 + threadIdx.x;
    int b = i / DIM;
    float s = 0.f;
    #pragma unroll
    for (int p = 0; p < NSPLIT; p++) s += g_partial[(b * NSPLIT + p) * DIM + (i % DIM)];
    g_xavg[i] = s * (1.0f / SEQ);
}

__global__ void kavg_kernel(const float* __restrict__ wk) {
    int w = (blockIdx.x * blockDim.x + threadIdx.x) >> 5;
    int lane = threadIdx.x & 31;
    int b = w / DIM, co = w % DIM;
    const float* wr = wk + (size_t)co * DIM;
    const float* xa = g_xavg + b * DIM;
    float s = 0.f;
    #pragma unroll 4
    for (int c = lane; c < DIM; c += 32) s += wr[c] * xa[c];
    #pragma unroll
    for (int o = 16; o > 0; o >>= 1) s += __shfl_xor_sync(0xffffffffu, s, o);
    if (lane == 0) g_kavg[b * DIM + co] = s;
}

__global__ void u_kernel(const float* __restrict__ wq) {
    int c = blockIdx.x * 256 + threadIdx.x;
    int h = blockIdx.y, b = blockIdx.z;
    __shared__ float ka[HDIM];
    if (threadIdx.x < HDIM) ka[threadIdx.x] = g_kavg[b * DIM + h * HDIM + threadIdx.x];
    __syncthreads();
    float s = 0.f;
    #pragma unroll
    for (int d = 0; d < HDIM; d++) s += ka[d] * wq[(size_t)(h * HDIM + d) * DIM + c];
    g_u[(b * HEADS + h) * DIM + c] = s;
}

__global__ void z_kernel(const float* __restrict__ x) {
    int w = (blockIdx.x * blockDim.x + threadIdx.x) >> 5;
    int lane = threadIdx.x & 31;
    int n = w % SEQ;
    int bh = w / SEQ;
    int b = bh / HEADS;
    const float* xr = x + ((size_t)b * SEQ + n) * DIM;
    const float* ur = g_u + (size_t)bh * DIM;
    float s = 0.f;
    #pragma unroll 4
    for (int c = lane; c < DIM; c += 32) s += xr[c] * ur[c];
    #pragma unroll
    for (int o = 16; o > 0; o >>= 1) s += __shfl_xor_sync(0xffffffffu, s, o);
    if (lane == 0) g_z[w] = s * SCALE;
}

__global__ void softmax_kernel() {
    int bh = blockIdx.x;
    float* z = g_z + (size_t)bh * SEQ;
    __shared__ float red[256];
    int t = threadIdx.x;
    float m = -1e30f;
    for (int i = t; i < SEQ; i += 256) m = fmaxf(m, z[i]);
    red[t] = m; __syncthreads();
    for (int o = 128; o > 0; o >>= 1) { if (t < o) red[t] = fmaxf(red[t], red[t + o]); __syncthreads(); }
    m = red[0]; __syncthreads();
    float s = 0.f;
    for (int i = t; i < SEQ; i += 256) { float e = __expf(z[i] - m); z[i] = e; s += e; }
    red[t] = s; __syncthreads();
    for (int o = 128; o > 0; o >>= 1) { if (t < o) red[t] += red[t + o]; __syncthreads(); }
    float inv = 1.0f / red[0];
    for (int i = t; i < SEQ; i += 256) z[i] *= inv;
}

// ---------------- conversions ----------------
__global__ void split_f32(const float* __restrict__ in, bf16* __restrict__ hi, bf16* __restrict__ lo) {
    int i = blockIdx.x * 256 + threadIdx.x;
    float4 v = ((const float4*)in)[i];
    bf16 h0, l0, h1, l1, h2, l2, h3, l3;
    split1(v.x, h0, l0); split1(v.y, h1, l1); split1(v.z, h2, l2); split1(v.w, h3, l3);
    __nv_bfloat162* H = (__nv_bfloat162*)hi;
    __nv_bfloat162* L = (__nv_bfloat162*)lo;
    H[i * 2 + 0] = __halves2bfloat162(h0, h1);
    H[i * 2 + 1] = __halves2bfloat162(h2, h3);
    L[i * 2 + 0] = __halves2bfloat162(l0, l1);
    L[i * 2 + 1] = __halves2bfloat162(l2, l3);
}

// g_v [b][j][c] -> vt [bh][d][j]
__global__ void vt_convert() {
    __shared__ float ts[32][33];
    int j0 = blockIdx.x * 32, c0 = blockIdx.y * 32, b = blockIdx.z;
    int t = threadIdx.x;
    int r = t >> 5, cc = t & 31;
    #pragma unroll
    for (int it = 0; it < 4; it++) {
        ts[r + it * 8][cc] = g_v[((size_t)b * SEQ + j0 + r + it * 8) * DIM + c0 + cc];
    }
    __syncthreads();
    #pragma unroll
    for (int it = 0; it < 4; it++) {
        int crow = r + it * 8;
        int c = c0 + crow;
        int bh = b * HEADS + (c >> 6);
        int d = c & 63;
        float v = ts[cc][crow];
        bf16 h, l;
        split1(v, h, l);
        size_t o = ((size_t)bh * HDIM + d) * SEQ + j0 + cc;
        g_vthi[o] = h;
        g_vtlo[o] = l;
    }
}

__global__ void attn2_convert() {
    int bh = blockIdx.x;
    for (int t = threadIdx.x; t < 4224; t += 256) {
        float v = g_z[(size_t)bh * SEQ + (t & (SEQ - 1))];
        bf16 h, l;
        split1(v, h, l);
        g_a2hi[bh * 4224 + t] = h;
        g_a2lo[bh * 4224 + t] = l;
    }
}

// ---------------- split-bf16 tensor GEMM: C[4096,1024] = A @ W^T (+bias) ----------------
__global__ __launch_bounds__(256) void gemm_split(
    const bf16* __restrict__ Ahi, const bf16* __restrict__ Alo,
    const bf16* __restrict__ Whi, const bf16* __restrict__ Wlo,
    const float* __restrict__ bias, float* __restrict__ C)
{
    __shared__ bf16 As[2][128 * PPITCH];
    __shared__ bf16 Bs[2][128 * PPITCH];
    const int tid = threadIdx.x;
    const int lane = tid & 31;
    const int wid = tid >> 5;
    const int m0 = blockIdx.y * 128;
    const int n0 = blockIdx.x * 128;
    const int wm = (wid >> 2) * 64;
    const int wn = (wid & 3) * 32;
    const int lrow = tid >> 1;
    const int lcol = (tid & 1) * 16;
    const int g = lane >> 2;
    const int t4 = lane & 3;

    float acc[4][4][4];
    #pragma unroll
    for (int i = 0; i < 4; i++) {
        #pragma unroll
        for (int j = 0; j < 4; j++) {
            #pragma unroll
            for (int k = 0; k < 4; k++) acc[i][j][k] = 0.f;
        }
    }

    const int arow = wm + (lane & 15);
    const int acolsel = (lane >> 4) * 8;
    const int bgrp = lane >> 3;
    const int brow = wn + ((bgrp >> 1) * 8) + (lane & 7);
    const int bcolsel = (bgrp & 1) * 8;

    // prologue: stage 0 (phase 0 = hi*hi, kk = 0)
    {
        const bf16* Ap = Ahi + (size_t)(m0 + lrow) * DIM + lcol;
        const bf16* Wp = Whi + (size_t)(n0 + lrow) * DIM + lcol;
        uint4 pa0 = *(const uint4*)Ap;
        uint4 pa1 = *(const uint4*)(Ap + 8);
        uint4 pb0 = *(const uint4*)Wp;
        uint4 pb1 = *(const uint4*)(Wp + 8);
        *(uint4*)&As[0][lrow * PPITCH + lcol] = pa0;
        *(uint4*)&As[0][lrow * PPITCH + lcol + 8] = pa1;
        *(uint4*)&Bs[0][lrow * PPITCH + lcol] = pb0;
        *(uint4*)&Bs[0][lrow * PPITCH + lcol + 8] = pb1;
    }
    __syncthreads();

    for (int s = 0; s < 96; s++) {
        const int buf = s & 1;
        const int sn = s + 1;
        uint4 ra0, ra1, rb0, rb1;
        if (sn < 96) {
            const int ph = sn >> 5;
            const int kk = (sn & 31) * 32;
            const bf16* Asrc = (ph == 1) ? Alo : Ahi;
            const bf16* Wsrc = (ph == 2) ? Wlo : Whi;
            const bf16* Ap = Asrc + (size_t)(m0 + lrow) * DIM + kk + lcol;
            const bf16* Wp = Wsrc + (size_t)(n0 + lrow) * DIM + kk + lcol;
            ra0 = *(const uint4*)Ap;
            ra1 = *(const uint4*)(Ap + 8);
            rb0 = *(const uint4*)Wp;
            rb1 = *(const uint4*)(Wp + 8);
        }
        #pragma unroll
        for (int khb = 0; khb < 32; khb += 16) {
            unsigned af[4][4];
            #pragma unroll
            for (int mi = 0; mi < 4; mi++) {
                ldsm_x4(af[mi][0], af[mi][1], af[mi][2], af[mi][3],
                        smem_u32(&As[buf][(arow + mi * 16) * PPITCH + khb + acolsel]));
            }
            unsigned bfr[4][2];
            #pragma unroll
            for (int p = 0; p < 2; p++) {
                unsigned r0, r1, r2, r3;
                ldsm_x4(r0, r1, r2, r3,
                        smem_u32(&Bs[buf][(brow + p * 16) * PPITCH + khb + bcolsel]));
                bfr[p * 2 + 0][0] = r0; bfr[p * 2 + 0][1] = r1;
                bfr[p * 2 + 1][0] = r2; bfr[p * 2 + 1][1] = r3;
            }
            #pragma unroll
            for (int mi = 0; mi < 4; mi++) {
                #pragma unroll
                for (int ni = 0; ni < 4; ni++) {
                    mma_bf16(acc[mi][ni], af[mi][0], af[mi][1], af[mi][2], af[mi][3],
                             bfr[ni][0], bfr[ni][1]);
                }
            }
        }
        if (sn < 96) {
            const int nb = buf ^ 1;
            *(uint4*)&As[nb][lrow * PPITCH + lcol] = ra0;
            *(uint4*)&As[nb][lrow * PPITCH + lcol + 8] = ra1;
            *(uint4*)&Bs[nb][lrow * PPITCH + lcol] = rb0;
            *(uint4*)&Bs[nb][lrow * PPITCH + lcol + 8] = rb1;
        }
        __syncthreads();
    }

    #pragma unroll
    for (int mi = 0; mi < 4; mi++) {
        int row = m0 + wm + mi * 16 + g;
        #pragma unroll
        for (int ni = 0; ni < 4; ni++) {
            int col = n0 + wn + ni * 8 + 2 * t4;
            float2 v0 = make_float2(acc[mi][ni][0], acc[mi][ni][1]);
            float2 v1 = make_float2(acc[mi][ni][2], acc[mi][ni][3]);
            if (bias) {
                float2 bb = *(const float2*)&bias[col];
                v0.x += bb.x; v0.y += bb.y; v1.x += bb.x; v1.y += bb.y;
            }
            *(float2*)&C[(size_t)row * DIM + col] = v0;
            *(float2*)&C[(size_t)(row + 8) * DIM + col] = v1;
        }
    }
}

// ---------------- tensor-core circular conv ----------------
// out[i,d] = sum_j attn[(j-i) mod N] * v[j,d]; Toeplitz A read from smem window.
__global__ __launch_bounds__(256) void conv_mma() {
    __shared__ unsigned wps[2][160];
    __shared__ bf16 Bs[2][64 * PPITCH];
    const int tid = threadIdx.x;
    const int lane = tid & 31;
    const int wid = tid >> 5;
    const int i0 = blockIdx.x * 128;
    const int bh = blockIdx.y;
    const int b = bh >> 4;
    const int h = bh & 15;
    const int wm = (wid >> 1) * 32;
    const int wn = (wid & 1) * 32;
    const int g = lane >> 2;
    const int t4 = lane & 3;

    const unsigned short* a2h = (const unsigned short*)(g_a2hi + (size_t)bh * 4224);
    const unsigned short* a2l = (const unsigned short*)(g_a2lo + (size_t)bh * 4224);
    const bf16* vth = g_vthi + (size_t)bh * HDIM * SEQ;
    const bf16* vtl = g_vtlo + (size_t)bh * HDIM * SEQ;

    float acc[2][4][4];
    #pragma unroll
    for (int i = 0; i < 2; i++) {
        #pragma unroll
        for (int j = 0; j < 4; j++) {
            #pragma unroll
            for (int k = 0; k < 4; k++) acc[i][j][k] = 0.f;
        }
    }

    const int brd = tid >> 2;
    const int bjc = (tid & 3) * 8;
    const int bgrp = lane >> 3;
    const int brow = wn + ((bgrp >> 1) * 8) + (lane & 7);
    const int bcolsel = (bgrp & 1) * 8;

    // prologue: stage 0 (phase 0 = a_hi * v_hi, j0 = 0)
    {
        const int ws = 1921 - i0;
        if (tid < 160) {
            unsigned pw = (unsigned)a2h[ws + tid] | ((unsigned)a2h[ws + tid + 1] << 16);
            wps[0][tid] = pw;
        }
        uint4 pb = *(const uint4*)(vth + (size_t)brd * SEQ + bjc);
        *(uint4*)&Bs[0][brd * PPITCH + bjc] = pb;
    }
    __syncthreads();

    for (int s = 0; s < 192; s++) {
        const int buf = s & 1;
        const int sn = s + 1;
        unsigned wv = 0u;
        uint4 bv;
        if (sn < 192) {
            const int ph = sn >> 6;
            const int j0 = (sn & 63) * 32;
            const int ws = 1921 + j0 - i0;
            const unsigned short* asrc = (ph == 1) ? a2l : a2h;
            if (tid < 160) {
                wv = (unsigned)asrc[ws + tid] | ((unsigned)asrc[ws + tid + 1] << 16);
            }
            const bf16* vsrc = (ph == 2) ? vtl : vth;
            bv = *(const uint4*)(vsrc + (size_t)brd * SEQ + j0 + bjc);
        }
        #pragma unroll
        for (int khb = 0; khb < 32; khb += 16) {
            const int ub = 127 - (wm + g) + 2 * t4 + khb;
            unsigned fa0[2], fa1[2], fa2[2];
            #pragma unroll
            for (int mi = 0; mi < 2; mi++) {
                const int u = ub - mi * 16;
                fa0[mi] = wps[buf][u];
                fa1[mi] = wps[buf][u - 8];
                fa2[mi] = wps[buf][u + 8];
            }
            unsigned bfr[4][2];
            #pragma unroll
            for (int p = 0; p < 2; p++) {
                unsigned r0, r1, r2, r3;
                ldsm_x4(r0, r1, r2, r3,
                        smem_u32(&Bs[buf][(brow + p * 16) * PPITCH + khb + bcolsel]));
                bfr[p * 2 + 0][0] = r0; bfr[p * 2 + 0][1] = r1;
                bfr[p * 2 + 1][0] = r2; bfr[p * 2 + 1][1] = r3;
            }
            #pragma unroll
            for (int mi = 0; mi < 2; mi++) {
                #pragma unroll
                for (int ni = 0; ni < 4; ni++) {
                    mma_bf16(acc[mi][ni], fa0[mi], fa1[mi], fa2[mi], fa0[mi],
                             bfr[ni][0], bfr[ni][1]);
                }
            }
        }
        if (sn < 192) {
            const int nb = buf ^ 1;
            if (tid < 160) wps[nb][tid] = wv;
            *(uint4*)&Bs[nb][brd * PPITCH + bjc] = bv;
        }
        __syncthreads();
    }

    #pragma unroll
    for (int mi = 0; mi < 2; mi++) {
        int row = i0 + wm + mi * 16 + g;
        #pragma unroll
        for (int ni = 0; ni < 4; ni++) {
            int col = h * HDIM + wn + ni * 8 + 2 * t4;
            *(float2*)&g_outh[((size_t)b * SEQ + row) * DIM + col] =
                make_float2(acc[mi][ni][0], acc[mi][ni][1]);
            *(float2*)&g_outh[((size_t)b * SEQ + row + 8) * DIM + col] =
                make_float2(acc[mi][ni][2], acc[mi][ni][3]);
        }
    }
}

// ---------------- launch ----------------
extern "C" void kernel_launch(void* const* d_in, const int* in_sizes, int n_in,
                              void* d_out, int out_size) {
    const float* x  = (const float*)d_in[0];
    const float* wq = (const float*)d_in[1];
    const float* wk = (const float*)d_in[2];
    const float* wv = (const float*)d_in[3];
    const float* wp = (const float*)d_in[4];
    const float* bp = (const float*)d_in[5];
    float* out = (float*)d_out;

    void* p0; cudaGetSymbolAddress(&p0, g_v);    float* gv  = (float*)p0;
    void* p1; cudaGetSymbolAddress(&p1, g_outh); float* go  = (float*)p1;
    void* p2; cudaGetSymbolAddress(&p2, g_xhi);  bf16* xhi  = (bf16*)p2;
    void* p3; cudaGetSymbolAddress(&p3, g_xlo);  bf16* xlo  = (bf16*)p3;
    void* p4; cudaGetSymbolAddress(&p4, g_wvhi); bf16* wvhi = (bf16*)p4;
    void* p5; cudaGetSymbolAddress(&p5, g_wvlo); bf16* wvlo = (bf16*)p5;
    void* p6; cudaGetSymbolAddress(&p6, g_wphi); bf16* wphi = (bf16*)p6;
    void* p7; cudaGetSymbolAddress(&p7, g_wplo); bf16* wplo = (bf16*)p7;
    void* p8; cudaGetSymbolAddress(&p8, g_ohhi); bf16* ohhi = (bf16*)p8;
    void* p9; cudaGetSymbolAddress(&p9, g_ohlo); bf16* ohlo = (bf16*)p9;

    // attention-weight path
    colsum_part<<<dim3(DIM / 256, BATCH, NSPLIT), 256>>>(x);
    colsum_final<<<(BATCH * DIM) / 256, 256>>>();
    kavg_kernel<<<(BATCH * DIM * 32) / 256, 256>>>(wk);
    u_kernel<<<dim3(DIM / 256, HEADS, BATCH), 256>>>(wq);
    z_kernel<<<(BATCH * HEADS * SEQ * 32) / 256, 256>>>(x);
    softmax_kernel<<<BATCH * HEADS, 256>>>();
    attn2_convert<<<BATCH * HEADS, 256>>>();

    // splits
    split_f32<<<(MTOT * DIM) / 1024, 256>>>(x, xhi, xlo);
    split_f32<<<(DIM * DIM) / 1024, 256>>>(wv, wvhi, wvlo);
    split_f32<<<(DIM * DIM) / 1024, 256>>>(wp, wphi, wplo);

    // v projection (tensor)
    gemm_split<<<dim3(DIM / 128, MTOT / 128), 256>>>(xhi, xlo, wvhi, wvlo, (const float*)0, gv);

    // transpose + split v
    vt_convert<<<dim3(SEQ / 32, DIM / 32, BATCH), 256>>>();

    // circular conv (tensor)
    conv_mma<<<dim3(SEQ / 128, BATCH * HEADS), 256>>>();

    // split conv output; output projection (tensor) with bias
    split_f32<<<(MTOT * DIM) / 1024, 256>>>(go, ohhi, ohlo);
    gemm_split<<<dim3(DIM / 128, MTOT / 128), 256>>>(ohhi, ohlo, wphi, wplo, bp, out);
}

// round 4
// speedup vs baseline: 3.6500x; 1.0078x over previous
#include <cuda_runtime.h>
#include <cuda_bf16.h>
#include <cstdint>

#define BATCH 2
#define SEQ   2048
#define DIM   1024
#define HEADS 16
#define HDIM  64
#define SCALE 0.125f
#define NSPLIT 32
#define MTOT  4096
#define PPITCH 40

typedef __nv_bfloat16 bf16;

// ---------------- scratch ----------------
__device__ float g_partial[BATCH * NSPLIT * DIM];
__device__ float g_xavg[BATCH * DIM];
__device__ float g_kavg[BATCH * DIM];
__device__ float g_u[BATCH * HEADS * DIM];
__device__ float g_z[BATCH * HEADS * SEQ];

__device__ bf16 g_xhi[(size_t)MTOT * DIM];
__device__ bf16 g_xlo[(size_t)MTOT * DIM];
__device__ bf16 g_wvhi[DIM * DIM];
__device__ bf16 g_wvlo[DIM * DIM];
__device__ bf16 g_wphi[DIM * DIM];
__device__ bf16 g_wplo[DIM * DIM];
__device__ bf16 g_vthi[32 * HDIM * SEQ];
__device__ bf16 g_vtlo[32 * HDIM * SEQ];
__device__ bf16 g_a2hi[32 * 4224];
__device__ bf16 g_a2lo[32 * 4224];
__device__ bf16 g_ohhi[(size_t)MTOT * DIM];
__device__ bf16 g_ohlo[(size_t)MTOT * DIM];

// ---------------- PTX helpers ----------------
__device__ __forceinline__ unsigned smem_u32(const void* p) {
    return (unsigned)__cvta_generic_to_shared(p);
}

__device__ __forceinline__ void ldsm_x4(unsigned& r0, unsigned& r1, unsigned& r2, unsigned& r3, unsigned a) {
    asm volatile("ldmatrix.sync.aligned.m8n8.x4.shared.b16 {%0,%1,%2,%3}, [%4];"
                 : "=r"(r0), "=r"(r1), "=r"(r2), "=r"(r3) : "r"(a));
}

__device__ __forceinline__ void mma_bf16(float* c, unsigned a0, unsigned a1, unsigned a2, unsigned a3,
                                         unsigned b0, unsigned b1) {
    asm volatile("mma.sync.aligned.m16n8k16.row.col.f32.bf16.bf16.f32 "
                 "{%0,%1,%2,%3}, {%4,%5,%6,%7}, {%8,%9}, {%0,%1,%2,%3};"
                 : "+f"(c[0]), "+f"(c[1]), "+f"(c[2]), "+f"(c[3])
                 : "r"(a0), "r"(a1), "r"(a2), "r"(a3), "r"(b0), "r"(b1));
}

__device__ __forceinline__ void split1(float v, bf16& h, bf16& l) {
    h = __float2bfloat16(v);
    l = __float2bfloat16(v - __bfloat162float(h));
}

// ---------------- small attention-weight path ----------------
__global__ void colsum_part(const float* __restrict__ x) {
    int c = blockIdx.x * 256 + threadIdx.x;
    int b = blockIdx.y, s = blockIdx.z;
    const float* xp = x + ((size_t)b * SEQ + (size_t)s * (SEQ / NSPLIT)) * DIM + c;
    float sum = 0.f;
    #pragma unroll 8
    for (int n = 0; n < SEQ / NSPLIT; n++) sum += xp[(size_t)n * DIM];
    g_partial[(b * NSPLIT + s) * DIM + c] = sum;
}

__global__ void colsum_final() {
    int i = blockIdx.x * 256 + threadIdx.x;
    int b = i / DIM;
    float s = 0.f;
    #pragma unroll
    for (int p = 0; p < NSPLIT; p++) s += g_partial[(b * NSPLIT + p) * DIM + (i % DIM)];
    g_xavg[i] = s * (1.0f / SEQ);
}

__global__ void kavg_kernel(const float* __restrict__ wk) {
    int w = (blockIdx.x * blockDim.x + threadIdx.x) >> 5;
    int lane = threadIdx.x & 31;
    int b = w / DIM, co = w % DIM;
    const float* wr = wk + (size_t)co * DIM;
    const float* xa = g_xavg + b * DIM;
    float s = 0.f;
    #pragma unroll 4
    for (int c = lane; c < DIM; c += 32) s += wr[c] * xa[c];
    #pragma unroll
    for (int o = 16; o > 0; o >>= 1) s += __shfl_xor_sync(0xffffffffu, s, o);
    if (lane == 0) g_kavg[b * DIM + co] = s;
}

__global__ void u_kernel(const float* __restrict__ wq) {
    int c = blockIdx.x * 256 + threadIdx.x;
    int h = blockIdx.y, b = blockIdx.z;
    __shared__ float ka[HDIM];
    if (threadIdx.x < HDIM) ka[threadIdx.x] = g_kavg[b * DIM + h * HDIM + threadIdx.x];
    __syncthreads();
    float s = 0.f;
    #pragma unroll
    for (int d = 0; d < HDIM; d++) s += ka[d] * wq[(size_t)(h * HDIM + d) * DIM + c];
    g_u[(b * HEADS + h) * DIM + c] = s;
}

// z[b,h,n] = scale * x[b,n,:] . u[b,h,:]  — warp per row, u chunked in smem, x read once
__global__ __launch_bounds__(256) void z_kernel2(const float* __restrict__ x) {
    __shared__ float us[HEADS][136];
    int tid = threadIdx.x, lane = tid & 31, w = tid >> 5;
    int row = blockIdx.x * 8 + w;           // 0..4095
    int b = row >> 11;
    int n = row & (SEQ - 1);
    const float* xr = x + (size_t)row * DIM;
    const float* ub = g_u + (size_t)b * HEADS * DIM;

    float acc[HEADS];
    #pragma unroll
    for (int h = 0; h < HEADS; h++) acc[h] = 0.f;

    for (int kc = 0; kc < DIM; kc += 128) {
        for (int t = tid; t < HEADS * 128; t += 256) {
            us[t >> 7][t & 127] = ub[(t >> 7) * DIM + kc + (t & 127)];
        }
        __syncthreads();
        float4 xv = *(const float4*)(xr + kc + lane * 4);
        #pragma unroll
        for (int h = 0; h < HEADS; h++) {
            float4 uv = *(const float4*)&us[h][lane * 4];
            acc[h] += xv.x * uv.x + xv.y * uv.y + xv.z * uv.z + xv.w * uv.w;
        }
        __syncthreads();
    }
    #pragma unroll
    for (int h = 0; h < HEADS; h++) {
        float s = acc[h];
        #pragma unroll
        for (int o = 16; o > 0; o >>= 1) s += __shfl_xor_sync(0xffffffffu, s, o);
        if (lane == 0) g_z[((size_t)(b * HEADS + h)) * SEQ + n] = s * SCALE;
    }
}

// softmax over n per (b,h), in-place on g_z, then write padded split copies
__global__ void softmax_attn2() {
    int bh = blockIdx.x;
    float* z = g_z + (size_t)bh * SEQ;
    __shared__ float red[256];
    int t = threadIdx.x;
    float m = -1e30f;
    for (int i = t; i < SEQ; i += 256) m = fmaxf(m, z[i]);
    red[t] = m; __syncthreads();
    for (int o = 128; o > 0; o >>= 1) { if (t < o) red[t] = fmaxf(red[t], red[t + o]); __syncthreads(); }
    m = red[0]; __syncthreads();
    float s = 0.f;
    for (int i = t; i < SEQ; i += 256) { float e = __expf(z[i] - m); z[i] = e; s += e; }
    red[t] = s; __syncthreads();
    for (int o = 128; o > 0; o >>= 1) { if (t < o) red[t] += red[t + o]; __syncthreads(); }
    float inv = 1.0f / red[0];
    for (int i = t; i < SEQ; i += 256) z[i] *= inv;
    __syncthreads();
    for (int i = t; i < 4224; i += 256) {
        float v = z[i & (SEQ - 1)];
        bf16 h, l;
        split1(v, h, l);
        g_a2hi[bh * 4224 + i] = h;
        g_a2lo[bh * 4224 + i] = l;
    }
}

// ---------------- conversions ----------------
__global__ void split_f32(const float* __restrict__ in, bf16* __restrict__ hi, bf16* __restrict__ lo) {
    int i = blockIdx.x * 256 + threadIdx.x;
    float4 v = ((const float4*)in)[i];
    bf16 h0, l0, h1, l1, h2, l2, h3, l3;
    split1(v.x, h0, l0); split1(v.y, h1, l1); split1(v.z, h2, l2); split1(v.w, h3, l3);
    __nv_bfloat162* H = (__nv_bfloat162*)hi;
    __nv_bfloat162* L = (__nv_bfloat162*)lo;
    H[i * 2 + 0] = __halves2bfloat162(h0, h1);
    H[i * 2 + 1] = __halves2bfloat162(h2, h3);
    L[i * 2 + 0] = __halves2bfloat162(l0, l1);
    L[i * 2 + 1] = __halves2bfloat162(l2, l3);
}

// ---------------- split-bf16 tensor GEMM: 4096x1024 = A @ W^T ----------------
// mode 0: C = fp32 out with bias.  mode 1: write transposed split bf16 into g_vthi/g_vtlo.
__global__ __launch_bounds__(256) void gemm_split(
    const bf16* __restrict__ Ahi, const bf16* __restrict__ Alo,
    const bf16* __restrict__ Whi, const bf16* __restrict__ Wlo,
    const float* __restrict__ bias, float* __restrict__ C, int mode)
{
    __shared__ bf16 As[2][128 * PPITCH];
    __shared__ bf16 Bs[2][128 * PPITCH];
    const int tid = threadIdx.x;
    const int lane = tid & 31;
    const int wid = tid >> 5;
    const int m0 = blockIdx.y * 128;
    const int n0 = blockIdx.x * 128;
    const int wm = (wid >> 2) * 64;
    const int wn = (wid & 3) * 32;
    const int lrow = tid >> 1;
    const int lcol = (tid & 1) * 16;
    const int g = lane >> 2;
    const int t4 = lane & 3;

    float acc[4][4][4];
    #pragma unroll
    for (int i = 0; i < 4; i++)
        #pragma unroll
        for (int j = 0; j < 4; j++)
            #pragma unroll
            for (int k = 0; k < 4; k++) acc[i][j][k] = 0.f;

    const int arow = wm + (lane & 15);
    const int acolsel = (lane >> 4) * 8;
    const int bgrp = lane >> 3;
    const int brow = wn + ((bgrp >> 1) * 8) + (lane & 7);
    const int bcolsel = (bgrp & 1) * 8;

    {
        const bf16* Ap = Ahi + (size_t)(m0 + lrow) * DIM + lcol;
        const bf16* Wp = Whi + (size_t)(n0 + lrow) * DIM + lcol;
        uint4 pa0 = *(const uint4*)Ap;
        uint4 pa1 = *(const uint4*)(Ap + 8);
        uint4 pb0 = *(const uint4*)Wp;
        uint4 pb1 = *(const uint4*)(Wp + 8);
        *(uint4*)&As[0][lrow * PPITCH + lcol] = pa0;
        *(uint4*)&As[0][lrow * PPITCH + lcol + 8] = pa1;
        *(uint4*)&Bs[0][lrow * PPITCH + lcol] = pb0;
        *(uint4*)&Bs[0][lrow * PPITCH + lcol + 8] = pb1;
    }
    __syncthreads();

    for (int s = 0; s < 96; s++) {
        const int buf = s & 1;
        const int sn = s + 1;
        uint4 ra0, ra1, rb0, rb1;
        if (sn < 96) {
            const int ph = sn >> 5;
            const int kk = (sn & 31) * 32;
            const bf16* Asrc = (ph == 1) ? Alo : Ahi;
            const bf16* Wsrc = (ph == 2) ? Wlo : Whi;
            const bf16* Ap = Asrc + (size_t)(m0 + lrow) * DIM + kk + lcol;
            const bf16* Wp = Wsrc + (size_t)(n0 + lrow) * DIM + kk + lcol;
            ra0 = *(const uint4*)Ap;
            ra1 = *(const uint4*)(Ap + 8);
            rb0 = *(const uint4*)Wp;
            rb1 = *(const uint4*)(Wp + 8);
        }
        #pragma unroll
        for (int khb = 0; khb < 32; khb += 16) {
            unsigned af[4][4];
            #pragma unroll
            for (int mi = 0; mi < 4; mi++) {
                ldsm_x4(af[mi][0], af[mi][1], af[mi][2], af[mi][3],
                        smem_u32(&As[buf][(arow + mi * 16) * PPITCH + khb + acolsel]));
            }
            unsigned bfr[4][2];
            #pragma unroll
            for (int p = 0; p < 2; p++) {
                unsigned r0, r1, r2, r3;
                ldsm_x4(r0, r1, r2, r3,
                        smem_u32(&Bs[buf][(brow + p * 16) * PPITCH + khb + bcolsel]));
                bfr[p * 2 + 0][0] = r0; bfr[p * 2 + 0][1] = r1;
                bfr[p * 2 + 1][0] = r2; bfr[p * 2 + 1][1] = r3;
            }
            #pragma unroll
            for (int mi = 0; mi < 4; mi++)
                #pragma unroll
                for (int ni = 0; ni < 4; ni++)
                    mma_bf16(acc[mi][ni], af[mi][0], af[mi][1], af[mi][2], af[mi][3],
                             bfr[ni][0], bfr[ni][1]);
        }
        if (sn < 96) {
            const int nb = buf ^ 1;
            *(uint4*)&As[nb][lrow * PPITCH + lcol] = ra0;
            *(uint4*)&As[nb][lrow * PPITCH + lcol + 8] = ra1;
            *(uint4*)&Bs[nb][lrow * PPITCH + lcol] = rb0;
            *(uint4*)&Bs[nb][lrow * PPITCH + lcol + 8] = rb1;
        }
        __syncthreads();
    }

    if (mode == 0) {
        #pragma unroll
        for (int mi = 0; mi < 4; mi++) {
            int row = m0 + wm + mi * 16 + g;
            #pragma unroll
            for (int ni = 0; ni < 4; ni++) {
                int col = n0 + wn + ni * 8 + 2 * t4;
                float2 bb = *(const float2*)&bias[col];
                float2 v0 = make_float2(acc[mi][ni][0] + bb.x, acc[mi][ni][1] + bb.y);
                float2 v1 = make_float2(acc[mi][ni][2] + bb.x, acc[mi][ni][3] + bb.y);
                *(float2*)&C[(size_t)row * DIM + col] = v0;
                *(float2*)&C[(size_t)(row + 8) * DIM + col] = v1;
            }
        }
    } else {
        // transposed split epilogue: value at (row=j_global, col=c) -> vt[bh][d][j]
        #pragma unroll
        for (int mi = 0; mi < 4; mi++) {
            int row = m0 + wm + mi * 16 + g;
            int b = row >> 11;
            int j = row & (SEQ - 1);
            #pragma unroll
            for (int ni = 0; ni < 4; ni++) {
                int col = n0 + wn + ni * 8 + 2 * t4;
                #pragma unroll
                for (int q = 0; q < 4; q++) {
                    int cc = col + (q & 1);
                    int jj = j + (q >> 1) * 8;
                    size_t idx = (((size_t)(b * HEADS + (cc >> 6))) * HDIM + (cc & 63)) * SEQ + jj;
                    bf16 h, l;
                    split1(acc[mi][ni][q], h, l);
                    g_vthi[idx] = h;
                    g_vtlo[idx] = l;
                }
            }
        }
    }
}

// ---------------- tensor-core circular conv (writes split bf16 directly) ----------------
__global__ __launch_bounds__(256) void conv_mma() {
    __shared__ unsigned wps[2][160];
    __shared__ bf16 Bs[2][64 * PPITCH];
    const int tid = threadIdx.x;
    const int lane = tid & 31;
    const int wid = tid >> 5;
    const int i0 = blockIdx.x * 128;
    const int bh = blockIdx.y;
    const int b = bh >> 4;
    const int h = bh & 15;
    const int wm = (wid >> 1) * 32;
    const int wn = (wid & 1) * 32;
    const int g = lane >> 2;
    const int t4 = lane & 3;

    const unsigned short* a2h = (const unsigned short*)(g_a2hi + (size_t)bh * 4224);
    const unsigned short* a2l = (const unsigned short*)(g_a2lo + (size_t)bh * 4224);
    const bf16* vth = g_vthi + (size_t)bh * HDIM * SEQ;
    const bf16* vtl = g_vtlo + (size_t)bh * HDIM * SEQ;

    float acc[2][4][4];
    #pragma unroll
    for (int i = 0; i < 2; i++)
        #pragma unroll
        for (int j = 0; j < 4; j++)
            #pragma unroll
            for (int k = 0; k < 4; k++) acc[i][j][k] = 0.f;

    const int brd = tid >> 2;
    const int bjc = (tid & 3) * 8;
    const int bgrp = lane >> 3;
    const int brow = wn + ((bgrp >> 1) * 8) + (lane & 7);
    const int bcolsel = (bgrp & 1) * 8;

    {
        const int ws = 1921 - i0;
        if (tid < 160) {
            unsigned pw = (unsigned)a2h[ws + tid] | ((unsigned)a2h[ws + tid + 1] << 16);
            wps[0][tid] = pw;
        }
        uint4 pb = *(const uint4*)(vth + (size_t)brd * SEQ + bjc);
        *(uint4*)&Bs[0][brd * PPITCH + bjc] = pb;
    }
    __syncthreads();

    for (int s = 0; s < 192; s++) {
        const int buf = s & 1;
        const int sn = s + 1;
        unsigned wv = 0u;
        uint4 bv;
        if (sn < 192) {
            const int ph = sn >> 6;
            const int j0 = (sn & 63) * 32;
            const int ws = 1921 + j0 - i0;
            const unsigned short* asrc = (ph == 1) ? a2l : a2h;
            if (tid < 160) {
                wv = (unsigned)asrc[ws + tid] | ((unsigned)asrc[ws + tid + 1] << 16);
            }
            const bf16* vsrc = (ph == 2) ? vtl : vth;
            bv = *(const uint4*)(vsrc + (size_t)brd * SEQ + j0 + bjc);
        }
        #pragma unroll
        for (int khb = 0; khb < 32; khb += 16) {
            const int ub = 127 - (wm + g) + 2 * t4 + khb;
            unsigned fa0[2], fa1[2], fa2[2];
            #pragma unroll
            for (int mi = 0; mi < 2; mi++) {
                const int u = ub - mi * 16;
                fa0[mi] = wps[buf][u];
                fa1[mi] = wps[buf][u - 8];
                fa2[mi] = wps[buf][u + 8];
            }
            unsigned bfr[4][2];
            #pragma unroll
            for (int p = 0; p < 2; p++) {
                unsigned r0, r1, r2, r3;
                ldsm_x4(r0, r1, r2, r3,
                        smem_u32(&Bs[buf][(brow + p * 16) * PPITCH + khb + bcolsel]));
                bfr[p * 2 + 0][0] = r0; bfr[p * 2 + 0][1] = r1;
                bfr[p * 2 + 1][0] = r2; bfr[p * 2 + 1][1] = r3;
            }
            #pragma unroll
            for (int mi = 0; mi < 2; mi++)
                #pragma unroll
                for (int ni = 0; ni < 4; ni++)
                    mma_bf16(acc[mi][ni], fa0[mi], fa1[mi], fa2[mi], fa0[mi],
                             bfr[ni][0], bfr[ni][1]);
        }
        if (sn < 192) {
            const int nb = buf ^ 1;
            if (tid < 160) wps[nb][tid] = wv;
            *(uint4*)&Bs[nb][brd * PPITCH + bjc] = bv;
        }
        __syncthreads();
    }

    // split epilogue: write oh hi/lo bf16 directly
    #pragma unroll
    for (int mi = 0; mi < 2; mi++) {
        int row = i0 + wm + mi * 16 + g;
        #pragma unroll
        for (int ni = 0; ni < 4; ni++) {
            int col = h * HDIM + wn + ni * 8 + 2 * t4;
            bf16 h0, l0, h1, l1, h2, l2, h3, l3;
            split1(acc[mi][ni][0], h0, l0);
            split1(acc[mi][ni][1], h1, l1);
            split1(acc[mi][ni][2], h2, l2);
            split1(acc[mi][ni][3], h3, l3);
            size_t o0 = ((size_t)b * SEQ + row) * DIM + col;
            size_t o1 = ((size_t)b * SEQ + row + 8) * DIM + col;
            *(__nv_bfloat162*)&g_ohhi[o0] = __halves2bfloat162(h0, h1);
            *(__nv_bfloat162*)&g_ohlo[o0] = __halves2bfloat162(l0, l1);
            *(__nv_bfloat162*)&g_ohhi[o1] = __halves2bfloat162(h2, h3);
            *(__nv_bfloat162*)&g_ohlo[o1] = __halves2bfloat162(l2, l3);
        }
    }
}

// ---------------- launch ----------------
extern "C" void kernel_launch(void* const* d_in, const int* in_sizes, int n_in,
                              void* d_out, int out_size) {
    const float* x  = (const float*)d_in[0];
    const float* wq = (const float*)d_in[1];
    const float* wk = (const float*)d_in[2];
    const float* wv = (const float*)d_in[3];
    const float* wp = (const float*)d_in[4];
    const float* bp = (const float*)d_in[5];
    float* out = (float*)d_out;

    void* p2; cudaGetSymbolAddress(&p2, g_xhi);  bf16* xhi  = (bf16*)p2;
    void* p3; cudaGetSymbolAddress(&p3, g_xlo);  bf16* xlo  = (bf16*)p3;
    void* p4; cudaGetSymbolAddress(&p4, g_wvhi); bf16* wvhi = (bf16*)p4;
    void* p5; cudaGetSymbolAddress(&p5, g_wvlo); bf16* wvlo = (bf16*)p5;
    void* p6; cudaGetSymbolAddress(&p6, g_wphi); bf16* wphi = (bf16*)p6;
    void* p7; cudaGetSymbolAddress(&p7, g_wplo); bf16* wplo = (bf16*)p7;
    void* p8; cudaGetSymbolAddress(&p8, g_ohhi); bf16* ohhi = (bf16*)p8;
    void* p9; cudaGetSymbolAddress(&p9, g_ohlo); bf16* ohlo = (bf16*)p9;

    // 1-3: splits (independent of everything else)
    split_f32<<<(MTOT * DIM) / 1024, 256>>>(x, xhi, xlo);
    split_f32<<<(DIM * DIM) / 1024, 256>>>(wv, wvhi, wvlo);
    split_f32<<<(DIM * DIM) / 1024, 256>>>(wp, wphi, wplo);

    // 4-5: column sums (independent of GEMM)
    colsum_part<<<dim3(DIM / 256, BATCH, NSPLIT), 256>>>(x);
    colsum_final<<<(BATCH * DIM) / 256, 256>>>();

    // 6: v-projection GEMM, writes transposed split vt directly (ncu -s 5 lands here)
    gemm_split<<<dim3(DIM / 128, MTOT / 128), 256>>>(xhi, xlo, wvhi, wvlo,
                                                     (const float*)0, (float*)0, 1);

    // attention-weight path
    kavg_kernel<<<(BATCH * DIM * 32) / 256, 256>>>(wk);
    u_kernel<<<dim3(DIM / 256, HEADS, BATCH), 256>>>(wq);
    z_kernel2<<<MTOT / 8, 256>>>(x);
    softmax_attn2<<<BATCH * HEADS, 256>>>();

    // circular conv (tensor), writes split bf16 directly
    conv_mma<<<dim3(SEQ / 128, BATCH * HEADS), 256>>>();

    // output projection (tensor) with bias
    gemm_split<<<dim3(DIM / 128, MTOT / 128), 256>>>(ohhi, ohlo, wphi, wplo, bp, out, 0);
}

// round 6
// speedup vs baseline: 4.9483x; 1.3557x over previous
#include <cuda_runtime.h>
#include <cuda_fp16.h>
#include <cstdint>

#define BATCH 2
#define SEQ   2048
#define DIM   1024
#define HEADS 16
#define HDIM  64
#define SCALE 0.125f
#define NSPLIT 32
#define MTOT  4096
#define PPITCH 40

typedef __half h16;

// ---------------- scratch ----------------
__device__ float g_partial[BATCH * NSPLIT * DIM];
__device__ float g_xavg[BATCH * DIM];
__device__ float g_kavg[BATCH * DIM];
__device__ float g_u[BATCH * HEADS * DIM];
__device__ float g_z[BATCH * HEADS * SEQ];

__device__ h16 g_xhi[(size_t)MTOT * DIM];
__device__ h16 g_xlo[(size_t)MTOT * DIM];
__device__ h16 g_wvhi[DIM * DIM];
__device__ h16 g_wphi[DIM * DIM];
__device__ h16 g_vthi[32 * HDIM * SEQ];
__device__ h16 g_a2hi[32 * 4224];
__device__ h16 g_a2lo[32 * 4224];
__device__ h16 g_ohhi[(size_t)MTOT * DIM];
__device__ h16 g_ohlo[(size_t)MTOT * DIM];

// ---------------- PTX helpers ----------------
__device__ __forceinline__ unsigned smem_u32(const void* p) {
    return (unsigned)__cvta_generic_to_shared(p);
}

__device__ __forceinline__ void ldsm_x4(unsigned& r0, unsigned& r1, unsigned& r2, unsigned& r3, unsigned a) {
    asm volatile("ldmatrix.sync.aligned.m8n8.x4.shared.b16 {%0,%1,%2,%3}, [%4];"
                 : "=r"(r0), "=r"(r1), "=r"(r2), "=r"(r3) : "r"(a));
}

__device__ __forceinline__ void mma_f16(float* c, unsigned a0, unsigned a1, unsigned a2, unsigned a3,
                                        unsigned b0, unsigned b1) {
    asm volatile("mma.sync.aligned.m16n8k16.row.col.f32.f16.f16.f32 "
                 "{%0,%1,%2,%3}, {%4,%5,%6,%7}, {%8,%9}, {%0,%1,%2,%3};"
                 : "+f"(c[0]), "+f"(c[1]), "+f"(c[2]), "+f"(c[3])
                 : "r"(a0), "r"(a1), "r"(a2), "r"(a3), "r"(b0), "r"(b1));
}

__device__ __forceinline__ void split1(float v, h16& h, h16& l) {
    h = __float2half_rn(v);
    l = __float2half_rn(v - __half2float(h));
}

// ---------------- small attention-weight path ----------------
__global__ void colsum_part(const float* __restrict__ x) {
    int c = blockIdx.x * 256 + threadIdx.x;
    int b = blockIdx.y, s = blockIdx.z;
    const float* xp = x + ((size_t)b * SEQ + (size_t)s * (SEQ / NSPLIT)) * DIM + c;
    float sum = 0.f;
    #pragma unroll 8
    for (int n = 0; n < SEQ / NSPLIT; n++) sum += xp[(size_t)n * DIM];
    g_partial[(b * NSPLIT + s) * DIM + c] = sum;
}

__global__ void colsum_final() {
    int i = blockIdx.x * 256 + threadIdx.x;
    int b = i / DIM;
    float s = 0.f;
    #pragma unroll
    for (int p = 0; p < NSPLIT; p++) s += g_partial[(b * NSPLIT + p) * DIM + (i % DIM)];
    g_xavg[i] = s * (1.0f / SEQ);
}

__global__ void kavg_kernel(const float* __restrict__ wk) {
    int w = (blockIdx.x * blockDim.x + threadIdx.x) >> 5;
    int lane = threadIdx.x & 31;
    int b = w / DIM, co = w % DIM;
    const float* wr = wk + (size_t)co * DIM;
    const float* xa = g_xavg + b * DIM;
    float s = 0.f;
    #pragma unroll 4
    for (int c = lane; c < DIM; c += 32) s += wr[c] * xa[c];
    #pragma unroll
    for (int o = 16; o > 0; o >>= 1) s += __shfl_xor_sync(0xffffffffu, s, o);
    if (lane == 0) g_kavg[b * DIM + co] = s;
}

__global__ void u_kernel(const float* __restrict__ wq) {
    int c = blockIdx.x * 256 + threadIdx.x;
    int h = blockIdx.y, b = blockIdx.z;
    __shared__ float ka[HDIM];
    if (threadIdx.x < HDIM) ka[threadIdx.x] = g_kavg[b * DIM + h * HDIM + threadIdx.x];
    __syncthreads();
    float s = 0.f;
    #pragma unroll
    for (int d = 0; d < HDIM; d++) s += ka[d] * wq[(size_t)(h * HDIM + d) * DIM + c];
    g_u[(b * HEADS + h) * DIM + c] = s;
}

__global__ __launch_bounds__(256) void z_kernel2(const float* __restrict__ x) {
    __shared__ float us[HEADS][136];
    int tid = threadIdx.x, lane = tid & 31, w = tid >> 5;
    int row = blockIdx.x * 8 + w;
    int b = row >> 11;
    int n = row & (SEQ - 1);
    const float* xr = x + (size_t)row * DIM;
    const float* ub = g_u + (size_t)b * HEADS * DIM;

    float acc[HEADS];
    #pragma unroll
    for (int h = 0; h < HEADS; h++) acc[h] = 0.f;

    for (int kc = 0; kc < DIM; kc += 128) {
        for (int t = tid; t < HEADS * 128; t += 256) {
            us[t >> 7][t & 127] = ub[(t >> 7) * DIM + kc + (t & 127)];
        }
        __syncthreads();
        float4 xv = *(const float4*)(xr + kc + lane * 4);
        #pragma unroll
        for (int h = 0; h < HEADS; h++) {
            float4 uv = *(const float4*)&us[h][lane * 4];
            acc[h] += xv.x * uv.x + xv.y * uv.y + xv.z * uv.z + xv.w * uv.w;
        }
        __syncthreads();
    }
    #pragma unroll
    for (int h = 0; h < HEADS; h++) {
        float s = acc[h];
        #pragma unroll
        for (int o = 16; o > 0; o >>= 1) s += __shfl_xor_sync(0xffffffffu, s, o);
        if (lane == 0) g_z[((size_t)(b * HEADS + h)) * SEQ + n] = s * SCALE;
    }
}

__global__ void softmax_attn2() {
    int bh = blockIdx.x;
    float* z = g_z + (size_t)bh * SEQ;
    __shared__ float red[256];
    int t = threadIdx.x;
    float m = -1e30f;
    for (int i = t; i < SEQ; i += 256) m = fmaxf(m, z[i]);
    red[t] = m; __syncthreads();
    for (int o = 128; o > 0; o >>= 1) { if (t < o) red[t] = fmaxf(red[t], red[t + o]); __syncthreads(); }
    m = red[0]; __syncthreads();
    float s = 0.f;
    for (int i = t; i < SEQ; i += 256) { float e = __expf(z[i] - m); z[i] = e; s += e; }
    red[t] = s; __syncthreads();
    for (int o = 128; o > 0; o >>= 1) { if (t < o) red[t] += red[t + o]; __syncthreads(); }
    float inv = 1.0f / red[0];
    for (int i = t; i < SEQ; i += 256) z[i] *= inv;
    __syncthreads();
    for (int i = t; i < 4224; i += 256) {
        float v = z[i & (SEQ - 1)];
        h16 h, l;
        split1(v, h, l);
        g_a2hi[bh * 4224 + i] = h;
        g_a2lo[bh * 4224 + i] = l;
    }
}

// ---------------- conversions ----------------
__global__ void split_f32(const float* __restrict__ in, h16* __restrict__ hi, h16* __restrict__ lo) {
    int i = blockIdx.x * 256 + threadIdx.x;
    float4 v = ((const float4*)in)[i];
    h16 h0, l0, h1, l1, h2, l2, h3, l3;
    split1(v.x, h0, l0); split1(v.y, h1, l1); split1(v.z, h2, l2); split1(v.w, h3, l3);
    __half2* H = (__half2*)hi;
    __half2* L = (__half2*)lo;
    H[i * 2 + 0] = __halves2half2(h0, h1);
    H[i * 2 + 1] = __halves2half2(h2, h3);
    L[i * 2 + 0] = __halves2half2(l0, l1);
    L[i * 2 + 1] = __halves2half2(l2, l3);
}

__global__ void split_hi_only(const float* __restrict__ in, h16* __restrict__ hi) {
    int i = blockIdx.x * 256 + threadIdx.x;
    float4 v = ((const float4*)in)[i];
    __half2* H = (__half2*)hi;
    H[i * 2 + 0] = __halves2half2(__float2half_rn(v.x), __float2half_rn(v.y));
    H[i * 2 + 1] = __halves2half2(__float2half_rn(v.z), __float2half_rn(v.w));
}

// ---------------- split-fp16 tensor GEMM: 4096x1024 = A @ W^T (2 phases) ----------------
// C = (A_hi + A_lo) @ W_hi^T
// mode 0: fp32 out + bias.  mode 1: transposed fp16-hi into g_vthi[bh][d][j].
__global__ __launch_bounds__(256) void gemm_split(
    const h16* __restrict__ Ahi, const h16* __restrict__ Alo,
    const h16* __restrict__ Whi,
    const float* __restrict__ bias, float* __restrict__ C, int mode)
{
    __shared__ h16 As[2][128 * PPITCH];
    __shared__ h16 Bs[2][128 * PPITCH];
    const int tid = threadIdx.x;
    const int lane = tid & 31;
    const int wid = tid >> 5;
    const int m0 = blockIdx.y * 128;
    const int n0 = blockIdx.x * 128;
    const int wm = (wid >> 2) * 64;
    const int wn = (wid & 3) * 32;
    const int lrow = tid >> 1;
    const int lcol = (tid & 1) * 16;
    const int g = lane >> 2;
    const int t4 = lane & 3;

    float acc[4][4][4];
    #pragma unroll
    for (int i = 0; i < 4; i++)
        #pragma unroll
        for (int j = 0; j < 4; j++)
            #pragma unroll
            for (int k = 0; k < 4; k++) acc[i][j][k] = 0.f;

    const int arow = wm + (lane & 15);
    const int acolsel = (lane >> 4) * 8;
    const int bgrp = lane >> 3;
    const int brow = wn + ((bgrp >> 1) * 8) + (lane & 7);
    const int bcolsel = (bgrp & 1) * 8;

    // prologue: stage 0 (A_hi, kk = 0)
    {
        const h16* Ap = Ahi + (size_t)(m0 + lrow) * DIM + lcol;
        const h16* Wp = Whi + (size_t)(n0 + lrow) * DIM + lcol;
        uint4 pa0 = *(const uint4*)Ap;
        uint4 pa1 = *(const uint4*)(Ap + 8);
        uint4 pb0 = *(const uint4*)Wp;
        uint4 pb1 = *(const uint4*)(Wp + 8);
        *(uint4*)&As[0][lrow * PPITCH + lcol] = pa0;
        *(uint4*)&As[0][lrow * PPITCH + lcol + 8] = pa1;
        *(uint4*)&Bs[0][lrow * PPITCH + lcol] = pb0;
        *(uint4*)&Bs[0][lrow * PPITCH + lcol + 8] = pb1;
    }
    __syncthreads();

    for (int s = 0; s < 64; s++) {
        const int buf = s & 1;
        const int sn = s + 1;
        uint4 ra0, ra1, rb0, rb1;
        if (sn < 64) {
            const int ph = sn >> 5;
            const int kk = (sn & 31) * 32;
            const h16* Asrc = (ph == 1) ? Alo : Ahi;
            const h16* Ap = Asrc + (size_t)(m0 + lrow) * DIM + kk + lcol;
            const h16* Wp = Whi + (size_t)(n0 + lrow) * DIM + kk + lcol;
            ra0 = *(const uint4*)Ap;
            ra1 = *(const uint4*)(Ap + 8);
            rb0 = *(const uint4*)Wp;
            rb1 = *(const uint4*)(Wp + 8);
        }
        #pragma unroll
        for (int khb = 0; khb < 32; khb += 16) {
            unsigned af[4][4];
            #pragma unroll
            for (int mi = 0; mi < 4; mi++) {
                ldsm_x4(af[mi][0], af[mi][1], af[mi][2], af[mi][3],
                        smem_u32(&As[buf][(arow + mi * 16) * PPITCH + khb + acolsel]));
            }
            unsigned bfr[4][2];
            #pragma unroll
            for (int p = 0; p < 2; p++) {
                unsigned r0, r1, r2, r3;
                ldsm_x4(r0, r1, r2, r3,
                        smem_u32(&Bs[buf][(brow + p * 16) * PPITCH + khb + bcolsel]));
                bfr[p * 2 + 0][0] = r0; bfr[p * 2 + 0][1] = r1;
                bfr[p * 2 + 1][0] = r2; bfr[p * 2 + 1][1] = r3;
            }
            #pragma unroll
            for (int mi = 0; mi < 4; mi++)
                #pragma unroll
                for (int ni = 0; ni < 4; ni++)
                    mma_f16(acc[mi][ni], af[mi][0], af[mi][1], af[mi][2], af[mi][3],
                            bfr[ni][0], bfr[ni][1]);
        }
        if (sn < 64) {
            const int nb = buf ^ 1;
            *(uint4*)&As[nb][lrow * PPITCH + lcol] = ra0;
            *(uint4*)&As[nb][lrow * PPITCH + lcol + 8] = ra1;
            *(uint4*)&Bs[nb][lrow * PPITCH + lcol] = rb0;
            *(uint4*)&Bs[nb][lrow * PPITCH + lcol + 8] = rb1;
        }
        __syncthreads();
    }

    if (mode == 0) {
        #pragma unroll
        for (int mi = 0; mi < 4; mi++) {
            int row = m0 + wm + mi * 16 + g;
            #pragma unroll
            for (int ni = 0; ni < 4; ni++) {
                int col = n0 + wn + ni * 8 + 2 * t4;
                float2 bb = *(const float2*)&bias[col];
                float2 v0 = make_float2(acc[mi][ni][0] + bb.x, acc[mi][ni][1] + bb.y);
                float2 v1 = make_float2(acc[mi][ni][2] + bb.x, acc[mi][ni][3] + bb.y);
                *(float2*)&C[(size_t)row * DIM + col] = v0;
                *(float2*)&C[(size_t)(row + 8) * DIM + col] = v1;
            }
        }
    } else {
        // transposed epilogue: (row=j_global, col=c) -> vt_hi[bh][d][j]
        #pragma unroll
        for (int mi = 0; mi < 4; mi++) {
            int row = m0 + wm + mi * 16 + g;
            int b = row >> 11;
            int j = row & (SEQ - 1);
            #pragma unroll
            for (int ni = 0; ni < 4; ni++) {
                int col = n0 + wn + ni * 8 + 2 * t4;
                #pragma unroll
                for (int q = 0; q < 4; q++) {
                    int cc = col + (q & 1);
                    int jj = j + (q >> 1) * 8;
                    size_t idx = (((size_t)(b * HEADS + (cc >> 6))) * HDIM + (cc & 63)) * SEQ + jj;
                    g_vthi[idx] = __float2half_rn(acc[mi][ni][q]);
                }
            }
        }
    }
}

// ---------------- fp16 circular conv (2 phases: a_hi, a_lo vs v_hi) ----------------
__global__ __launch_bounds__(256) void conv_mma() {
    __shared__ unsigned wps[2][160];
    __shared__ h16 Bs[2][64 * PPITCH];
    const int tid = threadIdx.x;
    const int lane = tid & 31;
    const int wid = tid >> 5;
    const int i0 = blockIdx.x * 128;
    const int bh = blockIdx.y;
    const int b = bh >> 4;
    const int h = bh & 15;
    const int wm = (wid >> 1) * 32;
    const int wn = (wid & 1) * 32;
    const int g = lane >> 2;
    const int t4 = lane & 3;

    const unsigned short* a2h = (const unsigned short*)(g_a2hi + (size_t)bh * 4224);
    const unsigned short* a2l = (const unsigned short*)(g_a2lo + (size_t)bh * 4224);
    const h16* vth = g_vthi + (size_t)bh * HDIM * SEQ;

    float acc[2][4][4];
    #pragma unroll
    for (int i = 0; i < 2; i++)
        #pragma unroll
        for (int j = 0; j < 4; j++)
            #pragma unroll
            for (int k = 0; k < 4; k++) acc[i][j][k] = 0.f;

    const int brd = tid >> 2;
    const int bjc = (tid & 3) * 8;
    const int bgrp = lane >> 3;
    const int brow = wn + ((bgrp >> 1) * 8) + (lane & 7);
    const int bcolsel = (bgrp & 1) * 8;

    {
        const int ws = 1921 - i0;
        if (tid < 160) {
            unsigned pw = (unsigned)a2h[ws + tid] | ((unsigned)a2h[ws + tid + 1] << 16);
            wps[0][tid] = pw;
        }
        uint4 pb = *(const uint4*)(vth + (size_t)brd * SEQ + bjc);
        *(uint4*)&Bs[0][brd * PPITCH + bjc] = pb;
    }
    __syncthreads();

    for (int s = 0; s < 128; s++) {
        const int buf = s & 1;
        const int sn = s + 1;
        unsigned wv = 0u;
        uint4 bv;
        if (sn < 128) {
            const int ph = sn >> 6;
            const int j0 = (sn & 63) * 32;
            const int ws = 1921 + j0 - i0;
            const unsigned short* asrc = (ph == 1) ? a2l : a2h;
            if (tid < 160) {
                wv = (unsigned)asrc[ws + tid] | ((unsigned)asrc[ws + tid + 1] << 16);
            }
            bv = *(const uint4*)(vth + (size_t)brd * SEQ + j0 + bjc);
        }
        #pragma unroll
        for (int khb = 0; khb < 32; khb += 16) {
            const int ub = 127 - (wm + g) + 2 * t4 + khb;
            unsigned fa0[2], fa1[2], fa2[2];
            #pragma unroll
            for (int mi = 0; mi < 2; mi++) {
                const int u = ub - mi * 16;
                fa0[mi] = wps[buf][u];
                fa1[mi] = wps[buf][u - 8];
                fa2[mi] = wps[buf][u + 8];
            }
            unsigned bfr[4][2];
            #pragma unroll
            for (int p = 0; p < 2; p++) {
                unsigned r0, r1, r2, r3;
                ldsm_x4(r0, r1, r2, r3,
                        smem_u32(&Bs[buf][(brow + p * 16) * PPITCH + khb + bcolsel]));
                bfr[p * 2 + 0][0] = r0; bfr[p * 2 + 0][1] = r1;
                bfr[p * 2 + 1][0] = r2; bfr[p * 2 + 1][1] = r3;
            }
            #pragma unroll
            for (int mi = 0; mi < 2; mi++)
                #pragma unroll
                for (int ni = 0; ni < 4; ni++)
                    mma_f16(acc[mi][ni], fa0[mi], fa1[mi], fa2[mi], fa0[mi],
                            bfr[ni][0], bfr[ni][1]);
        }
        if (sn < 128) {
            const int nb = buf ^ 1;
            if (tid < 160) wps[nb][tid] = wv;
            *(uint4*)&Bs[nb][brd * PPITCH + bjc] = bv;
        }
        __syncthreads();
    }

    // split epilogue: write oh hi/lo fp16
    #pragma unroll
    for (int mi = 0; mi < 2; mi++) {
        int row = i0 + wm + mi * 16 + g;
        #pragma unroll
        for (int ni = 0; ni < 4; ni++) {
            int col = h * HDIM + wn + ni * 8 + 2 * t4;
            h16 h0, l0, h1, l1, h2, l2, h3, l3;
            split1(acc[mi][ni][0], h0, l0);
            split1(acc[mi][ni][1], h1, l1);
            split1(acc[mi][ni][2], h2, l2);
            split1(acc[mi][ni][3], h3, l3);
            size_t o0 = ((size_t)b * SEQ + row) * DIM + col;
            size_t o1 = ((size_t)b * SEQ + row + 8) * DIM + col;
            *(__half2*)&g_ohhi[o0] = __halves2half2(h0, h1);
            *(__half2*)&g_ohlo[o0] = __halves2half2(l0, l1);
            *(__half2*)&g_ohhi[o1] = __halves2half2(h2, h3);
            *(__half2*)&g_ohlo[o1] = __halves2half2(l2, l3);
        }
    }
}

// ---------------- launch ----------------
extern "C" void kernel_launch(void* const* d_in, const int* in_sizes, int n_in,
                              void* d_out, int out_size) {
    const float* x  = (const float*)d_in[0];
    const float* wq = (const float*)d_in[1];
    const float* wk = (const float*)d_in[2];
    const float* wv = (const float*)d_in[3];
    const float* wp = (const float*)d_in[4];
    const float* bp = (const float*)d_in[5];
    float* out = (float*)d_out;

    void* p2; cudaGetSymbolAddress(&p2, g_xhi);  h16* xhi  = (h16*)p2;
    void* p3; cudaGetSymbolAddress(&p3, g_xlo);  h16* xlo  = (h16*)p3;
    void* p4; cudaGetSymbolAddress(&p4, g_wvhi); h16* wvhi = (h16*)p4;
    void* p6; cudaGetSymbolAddress(&p6, g_wphi); h16* wphi = (h16*)p6;
    void* p8; cudaGetSymbolAddress(&p8, g_ohhi); h16* ohhi = (h16*)p8;
    void* p9; cudaGetSymbolAddress(&p9, g_ohlo); h16* ohlo = (h16*)p9;

    // splits
    split_f32<<<(MTOT * DIM) / 1024, 256>>>(x, xhi, xlo);
    split_hi_only<<<(DIM * DIM) / 1024, 256>>>(wv, wvhi);
    split_hi_only<<<(DIM * DIM) / 1024, 256>>>(wp, wphi);

    // column sums
    colsum_part<<<dim3(DIM / 256, BATCH, NSPLIT), 256>>>(x);
    colsum_final<<<(BATCH * DIM) / 256, 256>>>();

    // v-projection (fp16 2-phase), writes transposed fp16 vt directly
    gemm_split<<<dim3(DIM / 128, MTOT / 128), 256>>>(xhi, xlo, wvhi,
                                                     (const float*)0, (float*)0, 1);

    // attention-weight path
    kavg_kernel<<<(BATCH * DIM * 32) / 256, 256>>>(wk);
    u_kernel<<<dim3(DIM / 256, HEADS, BATCH), 256>>>(wq);
    z_kernel2<<<MTOT / 8, 256>>>(x);
    softmax_attn2<<<BATCH * HEADS, 256>>>();

    // circular conv (fp16 2-phase), writes split fp16 oh
    conv_mma<<<dim3(SEQ / 128, BATCH * HEADS), 256>>>();

    // output projection (fp16 2-phase) with bias
    gemm_split<<<dim3(DIM / 128, MTOT / 128), 256>>>(ohhi, ohlo, wphi, bp, out, 0);
}

// round 7
// speedup vs baseline: 8.6497x; 1.7480x over previous
#include <cuda_runtime.h>
#include <cuda_fp16.h>
#include <cstdint>

#define BATCH 2
#define SEQ   2048
#define DIM   1024
#define HEADS 16
#define HDIM  64
#define SCALE 0.125f
#define NSPLIT 32
#define MTOT  4096
#define PPITCH 40

typedef __half h16;

// ---------------- scratch ----------------
__device__ float g_partial[BATCH * NSPLIT * DIM];
__device__ float g_xavg[BATCH * DIM];
__device__ float g_kavg[BATCH * DIM];
__device__ float g_u[BATCH * HEADS * DIM];
__device__ float g_z[BATCH * HEADS * SEQ];

__device__ h16 g_xhi[(size_t)MTOT * DIM];
__device__ h16 g_wvhi[DIM * DIM];
__device__ h16 g_wphi[DIM * DIM];
__device__ h16 g_vthi[32 * HDIM * SEQ];
__device__ h16 g_a2hi[32 * 4224];
__device__ h16 g_ohhi[(size_t)MTOT * DIM];

// ---------------- PTX helpers ----------------
__device__ __forceinline__ unsigned smem_u32(const void* p) {
    return (unsigned)__cvta_generic_to_shared(p);
}

__device__ __forceinline__ void ldsm_x4(unsigned& r0, unsigned& r1, unsigned& r2, unsigned& r3, unsigned a) {
    asm volatile("ldmatrix.sync.aligned.m8n8.x4.shared.b16 {%0,%1,%2,%3}, [%4];"
                 : "=r"(r0), "=r"(r1), "=r"(r2), "=r"(r3) : "r"(a));
}

__device__ __forceinline__ void mma_f16(float* c, unsigned a0, unsigned a1, unsigned a2, unsigned a3,
                                        unsigned b0, unsigned b1) {
    asm volatile("mma.sync.aligned.m16n8k16.row.col.f32.f16.f16.f32 "
                 "{%0,%1,%2,%3}, {%4,%5,%6,%7}, {%8,%9}, {%0,%1,%2,%3};"
                 : "+f"(c[0]), "+f"(c[1]), "+f"(c[2]), "+f"(c[3])
                 : "r"(a0), "r"(a1), "r"(a2), "r"(a3), "r"(b0), "r"(b1));
}

// ---------------- small attention-weight path ----------------
__global__ void colsum_part(const float* __restrict__ x) {
    int c = blockIdx.x * 256 + threadIdx.x;
    int b = blockIdx.y, s = blockIdx.z;
    const float* xp = x + ((size_t)b * SEQ + (size_t)s * (SEQ / NSPLIT)) * DIM + c;
    float sum = 0.f;
    #pragma unroll 8
    for (int n = 0; n < SEQ / NSPLIT; n++) sum += xp[(size_t)n * DIM];
    g_partial[(b * NSPLIT + s) * DIM + c] = sum;
}

__global__ void colsum_final() {
    int i = blockIdx.x * 256 + threadIdx.x;
    int b = i / DIM;
    float s = 0.f;
    #pragma unroll
    for (int p = 0; p < NSPLIT; p++) s += g_partial[(b * NSPLIT + p) * DIM + (i % DIM)];
    g_xavg[i] = s * (1.0f / SEQ);
}

__global__ void kavg_kernel(const float* __restrict__ wk) {
    int w = (blockIdx.x * blockDim.x + threadIdx.x) >> 5;
    int lane = threadIdx.x & 31;
    int b = w / DIM, co = w % DIM;
    const float* wr = wk + (size_t)co * DIM;
    const float* xa = g_xavg + b * DIM;
    float s = 0.f;
    #pragma unroll 4
    for (int c = lane; c < DIM; c += 32) s += wr[c] * xa[c];
    #pragma unroll
    for (int o = 16; o > 0; o >>= 1) s += __shfl_xor_sync(0xffffffffu, s, o);
    if (lane == 0) g_kavg[b * DIM + co] = s;
}

__global__ void u_kernel(const float* __restrict__ wq) {
    int c = blockIdx.x * 256 + threadIdx.x;
    int h = blockIdx.y, b = blockIdx.z;
    __shared__ float ka[HDIM];
    if (threadIdx.x < HDIM) ka[threadIdx.x] = g_kavg[b * DIM + h * HDIM + threadIdx.x];
    __syncthreads();
    float s = 0.f;
    #pragma unroll
    for (int d = 0; d < HDIM; d++) s += ka[d] * wq[(size_t)(h * HDIM + d) * DIM + c];
    g_u[(b * HEADS + h) * DIM + c] = s;
}

__global__ __launch_bounds__(256) void z_kernel2(const float* __restrict__ x) {
    __shared__ float us[HEADS][136];
    int tid = threadIdx.x, lane = tid & 31, w = tid >> 5;
    int row = blockIdx.x * 8 + w;
    int b = row >> 11;
    int n = row & (SEQ - 1);
    const float* xr = x + (size_t)row * DIM;
    const float* ub = g_u + (size_t)b * HEADS * DIM;

    float acc[HEADS];
    #pragma unroll
    for (int h = 0; h < HEADS; h++) acc[h] = 0.f;

    for (int kc = 0; kc < DIM; kc += 128) {
        for (int t = tid; t < HEADS * 128; t += 256) {
            us[t >> 7][t & 127] = ub[(t >> 7) * DIM + kc + (t & 127)];
        }
        __syncthreads();
        float4 xv = *(const float4*)(xr + kc + lane * 4);
        #pragma unroll
        for (int h = 0; h < HEADS; h++) {
            float4 uv = *(const float4*)&us[h][lane * 4];
            acc[h] += xv.x * uv.x + xv.y * uv.y + xv.z * uv.z + xv.w * uv.w;
        }
        __syncthreads();
    }
    #pragma unroll
    for (int h = 0; h < HEADS; h++) {
        float s = acc[h];
        #pragma unroll
        for (int o = 16; o > 0; o >>= 1) s += __shfl_xor_sync(0xffffffffu, s, o);
        if (lane == 0) g_z[((size_t)(b * HEADS + h)) * SEQ + n] = s * SCALE;
    }
}

__global__ void softmax_attn2() {
    int bh = blockIdx.x;
    float* z = g_z + (size_t)bh * SEQ;
    __shared__ float red[256];
    int t = threadIdx.x;
    float m = -1e30f;
    for (int i = t; i < SEQ; i += 256) m = fmaxf(m, z[i]);
    red[t] = m; __syncthreads();
    for (int o = 128; o > 0; o >>= 1) { if (t < o) red[t] = fmaxf(red[t], red[t + o]); __syncthreads(); }
    m = red[0]; __syncthreads();
    float s = 0.f;
    for (int i = t; i < SEQ; i += 256) { float e = __expf(z[i] - m); z[i] = e; s += e; }
    red[t] = s; __syncthreads();
    for (int o = 128; o > 0; o >>= 1) { if (t < o) red[t] += red[t + o]; __syncthreads(); }
    float inv = 1.0f / red[0];
    for (int i = t; i < SEQ; i += 256) z[i] *= inv;
    __syncthreads();
    for (int i = t; i < 4224; i += 256) {
        g_a2hi[bh * 4224 + i] = __float2half_rn(z[i & (SEQ - 1)]);
    }
}

// ---------------- conversions ----------------
__global__ void split_hi_only(const float* __restrict__ in, h16* __restrict__ hi) {
    int i = blockIdx.x * 256 + threadIdx.x;
    float4 v = ((const float4*)in)[i];
    __half2* H = (__half2*)hi;
    H[i * 2 + 0] = __halves2half2(__float2half_rn(v.x), __float2half_rn(v.y));
    H[i * 2 + 1] = __halves2half2(__float2half_rn(v.z), __float2half_rn(v.w));
}

// ---------------- fp16 tensor GEMM: 4096x1024 = A @ W^T (1 phase) ----------------
// mode 0: fp32 out + bias.  mode 1: transposed fp16 into g_vthi[bh][d][j].
__global__ __launch_bounds__(256) void gemm_split(
    const h16* __restrict__ Ahi, const h16* __restrict__ Whi,
    const float* __restrict__ bias, float* __restrict__ C, int mode)
{
    __shared__ h16 As[2][128 * PPITCH];
    __shared__ h16 Bs[2][128 * PPITCH];
    const int tid = threadIdx.x;
    const int lane = tid & 31;
    const int wid = tid >> 5;
    const int m0 = blockIdx.y * 128;
    const int n0 = blockIdx.x * 128;
    const int wm = (wid >> 2) * 64;
    const int wn = (wid & 3) * 32;
    const int lrow = tid >> 1;
    const int lcol = (tid & 1) * 16;
    const int g = lane >> 2;
    const int t4 = lane & 3;

    float acc[4][4][4];
    #pragma unroll
    for (int i = 0; i < 4; i++)
        #pragma unroll
        for (int j = 0; j < 4; j++)
            #pragma unroll
            for (int k = 0; k < 4; k++) acc[i][j][k] = 0.f;

    const int arow = wm + (lane & 15);
    const int acolsel = (lane >> 4) * 8;
    const int bgrp = lane >> 3;
    const int brow = wn + ((bgrp >> 1) * 8) + (lane & 7);
    const int bcolsel = (bgrp & 1) * 8;

    // prologue
    {
        const h16* Ap = Ahi + (size_t)(m0 + lrow) * DIM + lcol;
        const h16* Wp = Whi + (size_t)(n0 + lrow) * DIM + lcol;
        uint4 pa0 = *(const uint4*)Ap;
        uint4 pa1 = *(const uint4*)(Ap + 8);
        uint4 pb0 = *(const uint4*)Wp;
        uint4 pb1 = *(const uint4*)(Wp + 8);
        *(uint4*)&As[0][lrow * PPITCH + lcol] = pa0;
        *(uint4*)&As[0][lrow * PPITCH + lcol + 8] = pa1;
        *(uint4*)&Bs[0][lrow * PPITCH + lcol] = pb0;
        *(uint4*)&Bs[0][lrow * PPITCH + lcol + 8] = pb1;
    }
    __syncthreads();

    for (int s = 0; s < 32; s++) {
        const int buf = s & 1;
        const int sn = s + 1;
        uint4 ra0, ra1, rb0, rb1;
        if (sn < 32) {
            const int kk = sn * 32;
            const h16* Ap = Ahi + (size_t)(m0 + lrow) * DIM + kk + lcol;
            const h16* Wp = Whi + (size_t)(n0 + lrow) * DIM + kk + lcol;
            ra0 = *(const uint4*)Ap;
            ra1 = *(const uint4*)(Ap + 8);
            rb0 = *(const uint4*)Wp;
            rb1 = *(const uint4*)(Wp + 8);
        }
        #pragma unroll
        for (int khb = 0; khb < 32; khb += 16) {
            unsigned af[4][4];
            #pragma unroll
            for (int mi = 0; mi < 4; mi++) {
                ldsm_x4(af[mi][0], af[mi][1], af[mi][2], af[mi][3],
                        smem_u32(&As[buf][(arow + mi * 16) * PPITCH + khb + acolsel]));
            }
            unsigned bfr[4][2];
            #pragma unroll
            for (int p = 0; p < 2; p++) {
                unsigned r0, r1, r2, r3;
                ldsm_x4(r0, r1, r2, r3,
                        smem_u32(&Bs[buf][(brow + p * 16) * PPITCH + khb + bcolsel]));
                bfr[p * 2 + 0][0] = r0; bfr[p * 2 + 0][1] = r1;
                bfr[p * 2 + 1][0] = r2; bfr[p * 2 + 1][1] = r3;
            }
            #pragma unroll
            for (int mi = 0; mi < 4; mi++)
                #pragma unroll
                for (int ni = 0; ni < 4; ni++)
                    mma_f16(acc[mi][ni], af[mi][0], af[mi][1], af[mi][2], af[mi][3],
                            bfr[ni][0], bfr[ni][1]);
        }
        if (sn < 32) {
            const int nb = buf ^ 1;
            *(uint4*)&As[nb][lrow * PPITCH + lcol] = ra0;
            *(uint4*)&As[nb][lrow * PPITCH + lcol + 8] = ra1;
            *(uint4*)&Bs[nb][lrow * PPITCH + lcol] = rb0;
            *(uint4*)&Bs[nb][lrow * PPITCH + lcol + 8] = rb1;
        }
        __syncthreads();
    }

    if (mode == 0) {
        #pragma unroll
        for (int mi = 0; mi < 4; mi++) {
            int row = m0 + wm + mi * 16 + g;
            #pragma unroll
            for (int ni = 0; ni < 4; ni++) {
                int col = n0 + wn + ni * 8 + 2 * t4;
                float2 bb = *(const float2*)&bias[col];
                float2 v0 = make_float2(acc[mi][ni][0] + bb.x, acc[mi][ni][1] + bb.y);
                float2 v1 = make_float2(acc[mi][ni][2] + bb.x, acc[mi][ni][3] + bb.y);
                *(float2*)&C[(size_t)row * DIM + col] = v0;
                *(float2*)&C[(size_t)(row + 8) * DIM + col] = v1;
            }
        }
    } else {
        #pragma unroll
        for (int mi = 0; mi < 4; mi++) {
            int row = m0 + wm + mi * 16 + g;
            int b = row >> 11;
            int j = row & (SEQ - 1);
            #pragma unroll
            for (int ni = 0; ni < 4; ni++) {
                int col = n0 + wn + ni * 8 + 2 * t4;
                #pragma unroll
                for (int q = 0; q < 4; q++) {
                    int cc = col + (q & 1);
                    int jj = j + (q >> 1) * 8;
                    size_t idx = (((size_t)(b * HEADS + (cc >> 6))) * HDIM + (cc & 63)) * SEQ + jj;
                    g_vthi[idx] = __float2half_rn(acc[mi][ni][q]);
                }
            }
        }
    }
}

// ---------------- fp16 circular conv (1 phase) ----------------
__global__ __launch_bounds__(256) void conv_mma() {
    __shared__ unsigned wps[2][160];
    __shared__ h16 Bs[2][64 * PPITCH];
    const int tid = threadIdx.x;
    const int lane = tid & 31;
    const int wid = tid >> 5;
    const int i0 = blockIdx.x * 128;
    const int bh = blockIdx.y;
    const int b = bh >> 4;
    const int h = bh & 15;
    const int wm = (wid >> 1) * 32;
    const int wn = (wid & 1) * 32;
    const int g = lane >> 2;
    const int t4 = lane & 3;

    const unsigned short* a2h = (const unsigned short*)(g_a2hi + (size_t)bh * 4224);
    const h16* vth = g_vthi + (size_t)bh * HDIM * SEQ;

    float acc[2][4][4];
    #pragma unroll
    for (int i = 0; i < 2; i++)
        #pragma unroll
        for (int j = 0; j < 4; j++)
            #pragma unroll
            for (int k = 0; k < 4; k++) acc[i][j][k] = 0.f;

    const int brd = tid >> 2;
    const int bjc = (tid & 3) * 8;
    const int bgrp = lane >> 3;
    const int brow = wn + ((bgrp >> 1) * 8) + (lane & 7);
    const int bcolsel = (bgrp & 1) * 8;

    {
        const int ws = 1921 - i0;
        if (tid < 160) {
            unsigned pw = (unsigned)a2h[ws + tid] | ((unsigned)a2h[ws + tid + 1] << 16);
            wps[0][tid] = pw;
        }
        uint4 pb = *(const uint4*)(vth + (size_t)brd * SEQ + bjc);
        *(uint4*)&Bs[0][brd * PPITCH + bjc] = pb;
    }
    __syncthreads();

    for (int s = 0; s < 64; s++) {
        const int buf = s & 1;
        const int sn = s + 1;
        unsigned wv = 0u;
        uint4 bv;
        if (sn < 64) {
            const int j0 = sn * 32;
            const int ws = 1921 + j0 - i0;
            if (tid < 160) {
                wv = (unsigned)a2h[ws + tid] | ((unsigned)a2h[ws + tid + 1] << 16);
            }
            bv = *(const uint4*)(vth + (size_t)brd * SEQ + j0 + bjc);
        }
        #pragma unroll
        for (int khb = 0; khb < 32; khb += 16) {
            const int ub = 127 - (wm + g) + 2 * t4 + khb;
            unsigned fa0[2], fa1[2], fa2[2];
            #pragma unroll
            for (int mi = 0; mi < 2; mi++) {
                const int u = ub - mi * 16;
                fa0[mi] = wps[buf][u];
                fa1[mi] = wps[buf][u - 8];
                fa2[mi] = wps[buf][u + 8];
            }
            unsigned bfr[4][2];
            #pragma unroll
            for (int p = 0; p < 2; p++) {
                unsigned r0, r1, r2, r3;
                ldsm_x4(r0, r1, r2, r3,
                        smem_u32(&Bs[buf][(brow + p * 16) * PPITCH + khb + bcolsel]));
                bfr[p * 2 + 0][0] = r0; bfr[p * 2 + 0][1] = r1;
                bfr[p * 2 + 1][0] = r2; bfr[p * 2 + 1][1] = r3;
            }
            #pragma unroll
            for (int mi = 0; mi < 2; mi++)
                #pragma unroll
                for (int ni = 0; ni < 4; ni++)
                    mma_f16(acc[mi][ni], fa0[mi], fa1[mi], fa2[mi], fa0[mi],
                            bfr[ni][0], bfr[ni][1]);
        }
        if (sn < 64) {
            const int nb = buf ^ 1;
            if (tid < 160) wps[nb][tid] = wv;
            *(uint4*)&Bs[nb][brd * PPITCH + bjc] = bv;
        }
        __syncthreads();
    }

    #pragma unroll
    for (int mi = 0; mi < 2; mi++) {
        int row = i0 + wm + mi * 16 + g;
        #pragma unroll
        for (int ni = 0; ni < 4; ni++) {
            int col = h * HDIM + wn + ni * 8 + 2 * t4;
            size_t o0 = ((size_t)b * SEQ + row) * DIM + col;
            size_t o1 = ((size_t)b * SEQ + row + 8) * DIM + col;
            *(__half2*)&g_ohhi[o0] = __halves2half2(__float2half_rn(acc[mi][ni][0]),
                                                    __float2half_rn(acc[mi][ni][1]));
            *(__half2*)&g_ohhi[o1] = __halves2half2(__float2half_rn(acc[mi][ni][2]),
                                                    __float2half_rn(acc[mi][ni][3]));
        }
    }
}

// ---------------- launch ----------------
extern "C" void kernel_launch(void* const* d_in, const int* in_sizes, int n_in,
                              void* d_out, int out_size) {
    const float* x  = (const float*)d_in[0];
    const float* wq = (const float*)d_in[1];
    const float* wk = (const float*)d_in[2];
    const float* wv = (const float*)d_in[3];
    const float* wp = (const float*)d_in[4];
    const float* bp = (const float*)d_in[5];
    float* out = (float*)d_out;

    void* p2; cudaGetSymbolAddress(&p2, g_xhi);  h16* xhi  = (h16*)p2;
    void* p4; cudaGetSymbolAddress(&p4, g_wvhi); h16* wvhi = (h16*)p4;
    void* p6; cudaGetSymbolAddress(&p6, g_wphi); h16* wphi = (h16*)p6;
    void* p8; cudaGetSymbolAddress(&p8, g_ohhi); h16* ohhi = (h16*)p8;

    // converts
    split_hi_only<<<(MTOT * DIM) / 1024, 256>>>(x, xhi);
    split_hi_only<<<(DIM * DIM) / 1024, 256>>>(wv, wvhi);
    split_hi_only<<<(DIM * DIM) / 1024, 256>>>(wp, wphi);

    // column sums
    colsum_part<<<dim3(DIM / 256, BATCH, NSPLIT), 256>>>(x);
    colsum_final<<<(BATCH * DIM) / 256, 256>>>();

    // v-projection (fp16), writes transposed fp16 vt directly
    gemm_split<<<dim3(DIM / 128, MTOT / 128), 256>>>(xhi, wvhi,
                                                     (const float*)0, (float*)0, 1);

    // attention-weight path
    kavg_kernel<<<(BATCH * DIM * 32) / 256, 256>>>(wk);
    u_kernel<<<dim3(DIM / 256, HEADS, BATCH), 256>>>(wq);
    z_kernel2<<<MTOT / 8, 256>>>(x);
    softmax_attn2<<<BATCH * HEADS, 256>>>();

    // circular conv (fp16)
    conv_mma<<<dim3(SEQ / 128, BATCH * HEADS), 256>>>();

    // output projection (fp16) with bias
    gemm_split<<<dim3(DIM / 128, MTOT / 128), 256>>>(ohhi, wphi, bp, out, 0);
}

// round 8
// speedup vs baseline: 11.2770x; 1.3037x over previous
#include <cuda_runtime.h>
#include <cuda_fp16.h>
#include <cstdint>

#define BATCH 2
#define SEQ   2048
#define DIM   1024
#define HEADS 16
#define HDIM  64
#define SCALE 0.125f
#define MTOT  4096
#define PPITCH 40
#define CPITCH 72

typedef __half h16;

// ---------------- scratch ----------------
__device__ float g_partial[BATCH * 32 * DIM];
__device__ float g_xavg[BATCH * DIM];
__device__ float g_kavg[BATCH * DIM];
__device__ float g_u[BATCH * HEADS * DIM];
__device__ float g_z[BATCH * HEADS * SEQ];

__device__ h16 g_xhi[(size_t)MTOT * DIM];
__device__ h16 g_wvhi[DIM * DIM];
__device__ h16 g_wphi[DIM * DIM];
__device__ h16 g_vthi[32 * HDIM * SEQ];
__device__ h16 g_a2hi[32 * 4224];
__device__ h16 g_ohhi[(size_t)MTOT * DIM];

// ---------------- PTX helpers ----------------
__device__ __forceinline__ unsigned smem_u32(const void* p) {
    return (unsigned)__cvta_generic_to_shared(p);
}

__device__ __forceinline__ void ldsm_x4(unsigned& r0, unsigned& r1, unsigned& r2, unsigned& r3, unsigned a) {
    asm volatile("ldmatrix.sync.aligned.m8n8.x4.shared.b16 {%0,%1,%2,%3}, [%4];"
                 : "=r"(r0), "=r"(r1), "=r"(r2), "=r"(r3) : "r"(a));
}

__device__ __forceinline__ void mma_f16(float* c, unsigned a0, unsigned a1, unsigned a2, unsigned a3,
                                        unsigned b0, unsigned b1) {
    asm volatile("mma.sync.aligned.m16n8k16.row.col.f32.f16.f16.f32 "
                 "{%0,%1,%2,%3}, {%4,%5,%6,%7}, {%8,%9}, {%0,%1,%2,%3};"
                 : "+f"(c[0]), "+f"(c[1]), "+f"(c[2]), "+f"(c[3])
                 : "r"(a0), "r"(a1), "r"(a2), "r"(a3), "r"(b0), "r"(b1));
}

// ---------------- fused x split + partial column sums ----------------
__global__ void splitx_colsum(const float* __restrict__ x) {
    int c = blockIdx.x * 256 + threadIdx.x;
    int b = blockIdx.y, sz = blockIdx.z;
    const float* xp = x + ((size_t)b * SEQ + (size_t)sz * 64) * DIM + c;
    h16* hp = g_xhi + ((size_t)b * SEQ + (size_t)sz * 64) * DIM + c;
    float sum = 0.f;
    #pragma unroll 8
    for (int n = 0; n < 64; n++) {
        float v = xp[(size_t)n * DIM];
        sum += v;
        hp[(size_t)n * DIM] = __float2half_rn(v);
    }
    g_partial[(b * 32 + sz) * DIM + c] = sum;
}

__global__ void colsum_final() {
    int i = blockIdx.x * 256 + threadIdx.x;
    int b = i / DIM;
    float s = 0.f;
    #pragma unroll
    for (int p = 0; p < 32; p++) s += g_partial[(b * 32 + p) * DIM + (i % DIM)];
    g_xavg[i] = s * (1.0f / SEQ);
}

__global__ void kavg_kernel(const float* __restrict__ wk) {
    int w = (blockIdx.x * blockDim.x + threadIdx.x) >> 5;
    int lane = threadIdx.x & 31;
    int b = w / DIM, co = w % DIM;
    const float* wr = wk + (size_t)co * DIM;
    const float* xa = g_xavg + b * DIM;
    float s = 0.f;
    #pragma unroll 4
    for (int c = lane; c < DIM; c += 32) s += wr[c] * xa[c];
    #pragma unroll
    for (int o = 16; o > 0; o >>= 1) s += __shfl_xor_sync(0xffffffffu, s, o);
    if (lane == 0) g_kavg[b * DIM + co] = s;
}

__global__ void u_kernel(const float* __restrict__ wq) {
    int c = blockIdx.x * 256 + threadIdx.x;
    int h = blockIdx.y, b = blockIdx.z;
    __shared__ float ka[HDIM];
    if (threadIdx.x < HDIM) ka[threadIdx.x] = g_kavg[b * DIM + h * HDIM + threadIdx.x];
    __syncthreads();
    float s = 0.f;
    #pragma unroll
    for (int d = 0; d < HDIM; d++) s += ka[d] * wq[(size_t)(h * HDIM + d) * DIM + c];
    g_u[(b * HEADS + h) * DIM + c] = s;
}

// z from fp16 x (halved traffic)
__global__ __launch_bounds__(256) void z_kernel2() {
    __shared__ float us[HEADS][136];
    int tid = threadIdx.x, lane = tid & 31, w = tid >> 5;
    int row = blockIdx.x * 8 + w;
    int b = row >> 11;
    int n = row & (SEQ - 1);
    const __half2* xr = (const __half2*)(g_xhi + (size_t)row * DIM);
    const float* ub = g_u + (size_t)b * HEADS * DIM;

    float acc[HEADS];
    #pragma unroll
    for (int h = 0; h < HEADS; h++) acc[h] = 0.f;

    for (int kc = 0; kc < DIM; kc += 128) {
        for (int t = tid; t < HEADS * 128; t += 256) {
            us[t >> 7][t & 127] = ub[(t >> 7) * DIM + kc + (t & 127)];
        }
        __syncthreads();
        __half2 x01 = xr[(kc >> 1) + lane * 2];
        __half2 x23 = xr[(kc >> 1) + lane * 2 + 1];
        float2 f01 = __half22float2(x01);
        float2 f23 = __half22float2(x23);
        #pragma unroll
        for (int h = 0; h < HEADS; h++) {
            float4 uv = *(const float4*)&us[h][lane * 4];
            acc[h] += f01.x * uv.x + f01.y * uv.y + f23.x * uv.z + f23.y * uv.w;
        }
        __syncthreads();
    }
    #pragma unroll
    for (int h = 0; h < HEADS; h++) {
        float s = acc[h];
        #pragma unroll
        for (int o = 16; o > 0; o >>= 1) s += __shfl_xor_sync(0xffffffffu, s, o);
        if (lane == 0) g_z[((size_t)(b * HEADS + h)) * SEQ + n] = s * SCALE;
    }
}

__global__ void softmax_attn2() {
    int bh = blockIdx.x;
    float* z = g_z + (size_t)bh * SEQ;
    __shared__ float red[256];
    int t = threadIdx.x;
    float m = -1e30f;
    for (int i = t; i < SEQ; i += 256) m = fmaxf(m, z[i]);
    red[t] = m; __syncthreads();
    for (int o = 128; o > 0; o >>= 1) { if (t < o) red[t] = fmaxf(red[t], red[t + o]); __syncthreads(); }
    m = red[0]; __syncthreads();
    float s = 0.f;
    for (int i = t; i < SEQ; i += 256) { float e = __expf(z[i] - m); z[i] = e; s += e; }
    red[t] = s; __syncthreads();
    for (int o = 128; o > 0; o >>= 1) { if (t < o) red[t] += red[t + o]; __syncthreads(); }
    float inv = 1.0f / red[0];
    for (int i = t; i < SEQ; i += 256) z[i] *= inv;
    __syncthreads();
    for (int i = t; i < 4224; i += 256) {
        g_a2hi[bh * 4224 + i] = __float2half_rn(z[i & (SEQ - 1)]);
    }
}

__global__ void split_hi_only(const float* __restrict__ in, h16* __restrict__ hi) {
    int i = blockIdx.x * 256 + threadIdx.x;
    float4 v = ((const float4*)in)[i];
    __half2* H = (__half2*)hi;
    H[i * 2 + 0] = __halves2half2(__float2half_rn(v.x), __float2half_rn(v.y));
    H[i * 2 + 1] = __halves2half2(__float2half_rn(v.z), __float2half_rn(v.w));
}

// ---------------- fp16 tensor GEMM: 4096x1024 = A @ W^T, cp.async 3-stage ----------------
#define GSTAGE (128 * PPITCH)
__global__ __launch_bounds__(256, 2) void gemm_split(
    const h16* __restrict__ Ahi, const h16* __restrict__ Whi,
    const float* __restrict__ bias, float* __restrict__ C, int mode)
{
    extern __shared__ h16 gsm[];
    h16* As_ = gsm;                    // 3 stages of 128x40
    h16* Bs_ = gsm + 3 * GSTAGE;
    const int tid = threadIdx.x;
    const int lane = tid & 31;
    const int wid = tid >> 5;
    const int m0 = blockIdx.y * 128;
    const int n0 = blockIdx.x * 128;
    const int wm = (wid >> 2) * 64;
    const int wn = (wid & 3) * 32;
    const int g = lane >> 2;
    const int t4 = lane & 3;

    float acc[4][4][4];
    #pragma unroll
    for (int i = 0; i < 4; i++)
        #pragma unroll
        for (int j = 0; j < 4; j++)
            #pragma unroll
            for (int k = 0; k < 4; k++) acc[i][j][k] = 0.f;

    const int arow = wm + (lane & 15);
    const int acolsel = (lane >> 4) * 8;
    const int bgrp = lane >> 3;
    const int brow = wn + ((bgrp >> 1) * 8) + (lane & 7);
    const int bcolsel = (bgrp & 1) * 8;

    const int lr = tid >> 2;        // 0..63 (row pair base: handles rows lr and lr+64)
    const int lc16 = (tid & 3) * 8; // half offset within 32-half row

#define G_ISSUE(st_, s_) do {                                                        \
    const int kk_ = (s_) * 32;                                                       \
    unsigned sa0 = smem_u32(As_ + (st_) * GSTAGE + lr * PPITCH + lc16);              \
    const h16* ga0 = Ahi + (size_t)(m0 + lr) * DIM + kk_ + lc16;                     \
    asm volatile("cp.async.cg.shared.global [%0], [%1], 16;" :: "r"(sa0), "l"(ga0)); \
    unsigned sa1 = smem_u32(As_ + (st_) * GSTAGE + (lr + 64) * PPITCH + lc16);       \
    const h16* ga1 = Ahi + (size_t)(m0 + lr + 64) * DIM + kk_ + lc16;                \
    asm volatile("cp.async.cg.shared.global [%0], [%1], 16;" :: "r"(sa1), "l"(ga1)); \
    unsigned sb0 = smem_u32(Bs_ + (st_) * GSTAGE + lr * PPITCH + lc16);              \
    const h16* gb0 = Whi + (size_t)(n0 + lr) * DIM + kk_ + lc16;                     \
    asm volatile("cp.async.cg.shared.global [%0], [%1], 16;" :: "r"(sb0), "l"(gb0)); \
    unsigned sb1 = smem_u32(Bs_ + (st_) * GSTAGE + (lr + 64) * PPITCH + lc16);       \
    const h16* gb1 = Whi + (size_t)(n0 + lr + 64) * DIM + kk_ + lc16;                \
    asm volatile("cp.async.cg.shared.global [%0], [%1], 16;" :: "r"(sb1), "l"(gb1)); \
    asm volatile("cp.async.commit_group;");                                          \
} while (0)

    G_ISSUE(0, 0);

    for (int s = 0; s < 32; s++) {
        const int st = s % 3;
        if (s + 1 < 32) {
            G_ISSUE((s + 1) % 3, s + 1);
            asm volatile("cp.async.wait_group 1;");
        } else {
            asm volatile("cp.async.wait_group 0;");
        }
        __syncthreads();
        const h16* Ab = As_ + st * GSTAGE;
        const h16* Bb = Bs_ + st * GSTAGE;
        #pragma unroll
        for (int khb = 0; khb < 32; khb += 16) {
            unsigned af[4][4];
            #pragma unroll
            for (int mi = 0; mi < 4; mi++) {
                ldsm_x4(af[mi][0], af[mi][1], af[mi][2], af[mi][3],
                        smem_u32(Ab + (arow + mi * 16) * PPITCH + khb + acolsel));
            }
            unsigned bfr[4][2];
            #pragma unroll
            for (int p = 0; p < 2; p++) {
                unsigned r0, r1, r2, r3;
                ldsm_x4(r0, r1, r2, r3,
                        smem_u32(Bb + (brow + p * 16) * PPITCH + khb + bcolsel));
                bfr[p * 2 + 0][0] = r0; bfr[p * 2 + 0][1] = r1;
                bfr[p * 2 + 1][0] = r2; bfr[p * 2 + 1][1] = r3;
            }
            #pragma unroll
            for (int mi = 0; mi < 4; mi++)
                #pragma unroll
                for (int ni = 0; ni < 4; ni++)
                    mma_f16(acc[mi][ni], af[mi][0], af[mi][1], af[mi][2], af[mi][3],
                            bfr[ni][0], bfr[ni][1]);
        }
    }
#undef G_ISSUE

    if (mode == 0) {
        #pragma unroll
        for (int mi = 0; mi < 4; mi++) {
            int row = m0 + wm + mi * 16 + g;
            #pragma unroll
            for (int ni = 0; ni < 4; ni++) {
                int col = n0 + wn + ni * 8 + 2 * t4;
                float2 bb = *(const float2*)&bias[col];
                float2 v0 = make_float2(acc[mi][ni][0] + bb.x, acc[mi][ni][1] + bb.y);
                float2 v1 = make_float2(acc[mi][ni][2] + bb.x, acc[mi][ni][3] + bb.y);
                *(float2*)&C[(size_t)row * DIM + col] = v0;
                *(float2*)&C[(size_t)(row + 8) * DIM + col] = v1;
            }
        }
    } else {
        #pragma unroll
        for (int mi = 0; mi < 4; mi++) {
            int row = m0 + wm + mi * 16 + g;
            int b = row >> 11;
            int j = row & (SEQ - 1);
            #pragma unroll
            for (int ni = 0; ni < 4; ni++) {
                int col = n0 + wn + ni * 8 + 2 * t4;
                #pragma unroll
                for (int q = 0; q < 4; q++) {
                    int cc = col + (q & 1);
                    int jj = j + (q >> 1) * 8;
                    size_t idx = (((size_t)(b * HEADS + (cc >> 6))) * HDIM + (cc & 63)) * SEQ + jj;
                    g_vthi[idx] = __float2half_rn(acc[mi][ni][q]);
                }
            }
        }
    }
}

// ---------------- fp16 circular conv, BK=64 ----------------
__global__ __launch_bounds__(256) void conv_mma() {
    __shared__ unsigned wps[2][192];
    __shared__ h16 Bs[2][64 * CPITCH];
    const int tid = threadIdx.x;
    const int lane = tid & 31;
    const int wid = tid >> 5;
    const int i0 = blockIdx.x * 128;
    const int bh = blockIdx.y;
    const int b = bh >> 4;
    const int h = bh & 15;
    const int wm = (wid >> 1) * 32;
    const int wn = (wid & 1) * 32;
    const int g = lane >> 2;
    const int t4 = lane & 3;

    const unsigned short* a2h = (const unsigned short*)(g_a2hi + (size_t)bh * 4224);
    const h16* vth = g_vthi + (size_t)bh * HDIM * SEQ;

    float acc[2][4][4];
    #pragma unroll
    for (int i = 0; i < 2; i++)
        #pragma unroll
        for (int j = 0; j < 4; j++)
            #pragma unroll
            for (int k = 0; k < 4; k++) acc[i][j][k] = 0.f;

    // B tile loads: 64 rows x 64 halves = 512 x 16B; two per thread
    const int br0 = tid >> 3;            // rows 0..31
    const int bc16 = (tid & 7) * 8;      // half offset
    const int bgrp = lane >> 3;
    const int brow = wn + ((bgrp >> 1) * 8) + (lane & 7);
    const int bcolsel = (bgrp & 1) * 8;

    // prologue (j0 = 0)
    {
        const int ws = 1921 - i0;
        if (tid < 192) {
            wps[0][tid] = (unsigned)a2h[ws + tid] | ((unsigned)a2h[ws + tid + 1] << 16);
        }
        uint4 pb0 = *(const uint4*)(vth + (size_t)br0 * SEQ + bc16);
        uint4 pb1 = *(const uint4*)(vth + (size_t)(br0 + 32) * SEQ + bc16);
        *(uint4*)&Bs[0][br0 * CPITCH + bc16] = pb0;
        *(uint4*)&Bs[0][(br0 + 32) * CPITCH + bc16] = pb1;
    }
    __syncthreads();

    for (int s = 0; s < 32; s++) {
        const int buf = s & 1;
        const int sn = s + 1;
        unsigned wv = 0u;
        uint4 bv0, bv1;
        if (sn < 32) {
            const int j0 = sn * 64;
            const int ws = 1921 + j0 - i0;
            if (tid < 192) {
                wv = (unsigned)a2h[ws + tid] | ((unsigned)a2h[ws + tid + 1] << 16);
            }
            bv0 = *(const uint4*)(vth + (size_t)br0 * SEQ + j0 + bc16);
            bv1 = *(const uint4*)(vth + (size_t)(br0 + 32) * SEQ + j0 + bc16);
        }
        #pragma unroll
        for (int khb = 0; khb < 64; khb += 16) {
            const int ub = 127 - (wm + g) + 2 * t4 + khb;
            unsigned fa0[2], fa1[2], fa2[2];
            #pragma unroll
            for (int mi = 0; mi < 2; mi++) {
                const int u = ub - mi * 16;
                fa0[mi] = wps[buf][u];
                fa1[mi] = wps[buf][u - 8];
                fa2[mi] = wps[buf][u + 8];
            }
            unsigned bfr[4][2];
            #pragma unroll
            for (int p = 0; p < 2; p++) {
                unsigned r0, r1, r2, r3;
                ldsm_x4(r0, r1, r2, r3,
                        smem_u32(&Bs[buf][(brow + p * 16) * CPITCH + khb + bcolsel]));
                bfr[p * 2 + 0][0] = r0; bfr[p * 2 + 0][1] = r1;
                bfr[p * 2 + 1][0] = r2; bfr[p * 2 + 1][1] = r3;
            }
            #pragma unroll
            for (int mi = 0; mi < 2; mi++)
                #pragma unroll
                for (int ni = 0; ni < 4; ni++)
                    mma_f16(acc[mi][ni], fa0[mi], fa1[mi], fa2[mi], fa0[mi],
                            bfr[ni][0], bfr[ni][1]);
        }
        if (sn < 32) {
            const int nb = buf ^ 1;
            if (tid < 192) wps[nb][tid] = wv;
            *(uint4*)&Bs[nb][br0 * CPITCH + bc16] = bv0;
            *(uint4*)&Bs[nb][(br0 + 32) * CPITCH + bc16] = bv1;
        }
        __syncthreads();
    }

    #pragma unroll
    for (int mi = 0; mi < 2; mi++) {
        int row = i0 + wm + mi * 16 + g;
        #pragma unroll
        for (int ni = 0; ni < 4; ni++) {
            int col = h * HDIM + wn + ni * 8 + 2 * t4;
            size_t o0 = ((size_t)b * SEQ + row) * DIM + col;
            size_t o1 = ((size_t)b * SEQ + row + 8) * DIM + col;
            *(__half2*)&g_ohhi[o0] = __halves2half2(__float2half_rn(acc[mi][ni][0]),
                                                    __float2half_rn(acc[mi][ni][1]));
            *(__half2*)&g_ohhi[o1] = __halves2half2(__float2half_rn(acc[mi][ni][2]),
                                                    __float2half_rn(acc[mi][ni][3]));
        }
    }
}

// ---------------- launch ----------------
extern "C" void kernel_launch(void* const* d_in, const int* in_sizes, int n_in,
                              void* d_out, int out_size) {
    const float* x  = (const float*)d_in[0];
    const float* wq = (const float*)d_in[1];
    const float* wk = (const float*)d_in[2];
    const float* wv = (const float*)d_in[3];
    const float* wp = (const float*)d_in[4];
    const float* bp = (const float*)d_in[5];
    float* out = (float*)d_out;

    void* p2; cudaGetSymbolAddress(&p2, g_xhi);  h16* xhi  = (h16*)p2;
    void* p4; cudaGetSymbolAddress(&p4, g_wvhi); h16* wvhi = (h16*)p4;
    void* p6; cudaGetSymbolAddress(&p6, g_wphi); h16* wphi = (h16*)p6;
    void* p8; cudaGetSymbolAddress(&p8, g_ohhi); h16* ohhi = (h16*)p8;

    const int gemm_smem = 6 * GSTAGE * (int)sizeof(h16);   // 61440
    cudaFuncSetAttribute(gemm_split, cudaFuncAttributeMaxDynamicSharedMemorySize, gemm_smem);

    // fused x split + column partial sums; weight splits
    splitx_colsum<<<dim3(DIM / 256, BATCH, 32), 256>>>(x);
    split_hi_only<<<(DIM * DIM) / 1024, 256>>>(wv, wvhi);
    split_hi_only<<<(DIM * DIM) / 1024, 256>>>(wp, wphi);
    colsum_final<<<(BATCH * DIM) / 256, 256>>>();

    // v-projection (fp16 cp.async), writes transposed fp16 vt directly
    gemm_split<<<dim3(DIM / 128, MTOT / 128), 256, gemm_smem>>>(
        xhi, wvhi, (const float*)0, (float*)0, 1);

    // attention-weight path
    kavg_kernel<<<(BATCH * DIM * 32) / 256, 256>>>(wk);
    u_kernel<<<dim3(DIM / 256, HEADS, BATCH), 256>>>(wq);
    z_kernel2<<<MTOT / 8, 256>>>();
    softmax_attn2<<<BATCH * HEADS, 256>>>();

    // circular conv (fp16, BK=64)
    conv_mma<<<dim3(SEQ / 128, BATCH * HEADS), 256>>>();

    // output projection (fp16 cp.async) with bias
    gemm_split<<<dim3(DIM / 128, MTOT / 128), 256, gemm_smem>>>(ohhi, wphi, bp, out, 0);
}